// round 6
// baseline (speedup 1.0000x reference)
#include <cuda_runtime.h>
#include <math.h>
#include <stdint.h>

#define C_DIM   1024
#define H_NUM   16
#define DH      64
#define FF_DIM  4096
#define B_NUM   2
#define T_LEN   2048
#define M_TOK   4096   // B*T

// ---------------- scratch (device globals; no allocation allowed) ----------
__device__ float g_h  [M_TOK * C_DIM];
__device__ float g_qkv[M_TOK * 3 * C_DIM];
__device__ float g_q  [M_TOK * C_DIM];        // [B,H,T,dh]  (pre-scaled, tf32)
__device__ float g_k  [M_TOK * C_DIM];        // [B,H,T,dh]  (tf32)
__device__ float g_v  [M_TOK * C_DIM];        // [B,H,dh,T]  (transposed, tf32)
__device__ float g_o  [M_TOK * C_DIM];        // attention out, [B,T,H*dh]
__device__ float g_x1 [M_TOK * C_DIM];
__device__ float g_ff [M_TOK * FF_DIM];

// ---------------- helpers ----------------------------------------------------
__device__ __forceinline__ uint32_t f2tf32(float x) {
    uint32_t r;
    asm("cvt.rna.tf32.f32 %0, %1;" : "=r"(r) : "f"(x));
    return r;
}
__device__ __forceinline__ float tf32f(float x) { return __uint_as_float(f2tf32(x)); }

__device__ __forceinline__ void mma_tf32(float c[4],
                                         uint32_t a0, uint32_t a1, uint32_t a2, uint32_t a3,
                                         uint32_t b0, uint32_t b1) {
    asm volatile(
        "mma.sync.aligned.m16n8k8.row.col.f32.tf32.tf32.f32 "
        "{%0,%1,%2,%3}, {%4,%5,%6,%7}, {%8,%9}, {%0,%1,%2,%3};\n"
        : "+f"(c[0]), "+f"(c[1]), "+f"(c[2]), "+f"(c[3])
        : "r"(a0), "r"(a1), "r"(a2), "r"(a3), "r"(b0), "r"(b1));
}
__device__ __forceinline__ void ldsm4(uint32_t& r0, uint32_t& r1,
                                      uint32_t& r2, uint32_t& r3, uint32_t addr) {
    asm volatile("ldmatrix.sync.aligned.m8n8.x4.shared.b16 {%0,%1,%2,%3}, [%4];"
                 : "=r"(r0), "=r"(r1), "=r"(r2), "=r"(r3) : "r"(addr));
}
__device__ __forceinline__ void cp16(uint32_t dst, const void* src) {
    asm volatile("cp.async.cg.shared.global [%0], [%1], 16;" :: "r"(dst), "l"(src));
}

// ---------------- RMSNorm ----------------------------------------------------
__global__ void rmsnorm_kernel(const float* __restrict__ x,
                               const float* __restrict__ g,
                               float* __restrict__ y) {
    int row = blockIdx.x;
    int tid = threadIdx.x;
    const float4* xr = (const float4*)(x + (size_t)row * C_DIM);
    const float4* gr = (const float4*)g;
    float4*       yr = (float4*)(y + (size_t)row * C_DIM);

    float4 xv = xr[tid];
    float ss = xv.x*xv.x + xv.y*xv.y + xv.z*xv.z + xv.w*xv.w;
    #pragma unroll
    for (int off = 16; off > 0; off >>= 1)
        ss += __shfl_xor_sync(0xffffffffu, ss, off);
    __shared__ float red[8];
    if ((tid & 31) == 0) red[tid >> 5] = ss;
    __syncthreads();
    float tot = 0.f;
    #pragma unroll
    for (int i = 0; i < 8; i++) tot += red[i];
    float inv = rsqrtf(tot * (1.0f / C_DIM) + 1e-5f);

    float4 gv = gr[tid];
    float4 o;
    o.x = xv.x * gv.x * inv;
    o.y = xv.y * gv.y * inv;
    o.z = xv.z * gv.z * inv;
    o.w = xv.w * gv.w * inv;
    yr[tid] = o;
}

// ---------------- tf32 tensor-core GEMM: C[M,N] = A[M,K] @ W[N,K]^T ---------
// Block 128x128, BK=16, 4-stage cp.async pipeline (fast-tf32: raw fp32 bits).
// 8 warps (4m x 2n), warp tile 32x64, fragments via ldmatrix.x4.
// MODE 0: plain  MODE 1: +X residual  MODE 2: silu(X) * acc
#define GSTAGE   4
#define GTILE_B  4096u                 // one [128 rows][8 floats] q-tile, bytes
#define GSTAGE_B (2 * GTILE_B)         // 8 KB per stage (2 q-tiles)
#define GEMM_SMEM (2 * GSTAGE * GSTAGE_B)   // 64 KB (A then B)

template <int MODE>
__global__ __launch_bounds__(256, 2)
void tgemm_kernel(const float* __restrict__ A, const float* __restrict__ W,
                  const float* X, float* Cout, int M, int N, int K) {
    extern __shared__ float sm[];
    float* sA = sm;                          // GSTAGE * 2048 floats
    float* sB = sm + GSTAGE * 2048;

    int tid  = threadIdx.x;
    int bm   = blockIdx.y * 128;
    int bn   = blockIdx.x * 128;
    int warp = tid >> 5;
    int lane = tid & 31;
    int wm   = (warp >> 1) * 32;
    int wn   = (warp & 1) * 64;

    uint32_t aBase = (uint32_t)__cvta_generic_to_shared(sA);
    uint32_t bBase = (uint32_t)__cvta_generic_to_shared(sB);

    // per-thread cp.async mapping: 2 float4s of the 128x16 stage tile
    // idx = tid*2+j : row r = idx>>2, chunk c = idx&3 (k-offset 4c)
    uint32_t dstOff[2];
    int      rowJ[2], colJ[2];
    #pragma unroll
    for (int j = 0; j < 2; j++) {
        int idx = tid * 2 + j;
        int r = idx >> 2, c = idx & 3;
        int qt = c >> 1, ch = c & 1;
        dstOff[j] = qt * GTILE_B + (uint32_t)(r * 8 + ((ch ^ ((r >> 2) & 1)) << 2)) * 4u;
        rowJ[j] = r; colJ[j] = c * 4;
    }

    // ldmatrix per-thread byte offsets within one 4KB q-tile
    int i   = lane & 7;
    int sub = lane >> 3;
    uint32_t offA[2], offB[4];
    #pragma unroll
    for (int mt = 0; mt < 2; mt++) {
        int row = wm + mt * 16 + (sub & 1) * 8 + i;
        int ch  = (sub >> 1) ^ ((row >> 2) & 1);
        offA[mt] = (uint32_t)(row * 8 + ch * 4) * 4u;
    }
    #pragma unroll
    for (int p = 0; p < 4; p++) {
        int row = wn + p * 16 + (sub >> 1) * 8 + i;
        int ch  = (sub & 1) ^ ((row >> 2) & 1);
        offB[p] = (uint32_t)(row * 8 + ch * 4) * 4u;
    }

    float acc[2][8][4];
    #pragma unroll
    for (int mt = 0; mt < 2; mt++)
        #pragma unroll
        for (int nt = 0; nt < 8; nt++)
            #pragma unroll
            for (int e = 0; e < 4; e++) acc[mt][nt][e] = 0.f;

    int NC = K >> 4;   // k16 chunks

    auto load_chunk = [&](int ck, int st) {
        uint32_t aS = aBase + st * GSTAGE_B;
        uint32_t bS = bBase + st * GSTAGE_B;
        #pragma unroll
        for (int j = 0; j < 2; j++) {
            const float* as = A + (size_t)(bm + rowJ[j]) * K + ck * 16 + colJ[j];
            const float* bs = W + (size_t)(bn + rowJ[j]) * K + ck * 16 + colJ[j];
            cp16(aS + dstOff[j], as);
            cp16(bS + dstOff[j], bs);
        }
    };

    // prologue: stages 0..2
    #pragma unroll
    for (int s = 0; s < GSTAGE - 1; s++) {
        if (s < NC) load_chunk(s, s);
        asm volatile("cp.async.commit_group;" ::: "memory");
    }

    for (int ck = 0; ck < NC; ck++) {
        int st = ck & (GSTAGE - 1);
        asm volatile("cp.async.wait_group %0;" :: "n"(GSTAGE - 2) : "memory");
        __syncthreads();

        #pragma unroll
        for (int q = 0; q < 2; q++) {
            uint32_t tile = st * GSTAGE_B + q * GTILE_B;
            uint32_t aR[2][4], bR[4][4];
            ldsm4(aR[0][0], aR[0][1], aR[0][2], aR[0][3], aBase + tile + offA[0]);
            ldsm4(aR[1][0], aR[1][1], aR[1][2], aR[1][3], aBase + tile + offA[1]);
            #pragma unroll
            for (int p = 0; p < 4; p++)
                ldsm4(bR[p][0], bR[p][1], bR[p][2], bR[p][3], bBase + tile + offB[p]);
            #pragma unroll
            for (int mt = 0; mt < 2; mt++)
                #pragma unroll
                for (int nt = 0; nt < 8; nt++) {
                    int p  = nt >> 1;
                    int e0 = (nt & 1) * 2;
                    mma_tf32(acc[mt][nt],
                             aR[mt][0], aR[mt][1], aR[mt][2], aR[mt][3],
                             bR[p][e0], bR[p][e0 + 1]);
                }
        }

        int cn = ck + GSTAGE - 1;
        if (cn < NC) load_chunk(cn, cn & (GSTAGE - 1));
        asm volatile("cp.async.commit_group;" ::: "memory");
    }

    int g = lane >> 2;
    int t = lane & 3;
    #pragma unroll
    for (int mt = 0; mt < 2; mt++) {
        #pragma unroll
        for (int half = 0; half < 2; half++) {
            int row = bm + wm + mt * 16 + half * 8 + g;
            float*       crow = Cout + (size_t)row * N;
            const float* xrow = (MODE != 0) ? (X + (size_t)row * N) : nullptr;
            #pragma unroll
            for (int nt = 0; nt < 8; nt++) {
                int col = bn + wn + nt * 8 + 2 * t;
                float2 v;
                v.x = acc[mt][nt][half * 2 + 0];
                v.y = acc[mt][nt][half * 2 + 1];
                if (MODE == 1) {
                    float2 xv = *(const float2*)(xrow + col);
                    v.x += xv.x; v.y += xv.y;
                }
                if (MODE == 2) {
                    float2 xv = *(const float2*)(xrow + col);
                    v.x *= xv.x / (1.f + expf(-xv.x));
                    v.y *= xv.y / (1.f + expf(-xv.y));
                }
                *(float2*)(crow + col) = v;
            }
        }
    }
}

// ---------------- RoPE + split qkv -> q,k in [B,H,T,dh] (tf32, q pre-scaled)
#define Q_SCALE (0.125f * 1.44269504088896f)   // 1/sqrt(64) * log2(e)
__global__ void rope_split_kernel(const float* __restrict__ qkv,
                                  float* __restrict__ q,
                                  float* __restrict__ k) {
    int idx = blockIdx.x * blockDim.x + threadIdx.x;
    int i = idx & 31;
    int h = (idx >> 5) & 15;
    int m = idx >> 9;
    int b = m >> 11;
    int t = m & 2047;

    const float* base = qkv + (size_t)m * (3 * C_DIM) + h * DH + 2 * i;
    float q1 = base[0],     q2 = base[1];
    float k1 = base[C_DIM], k2 = base[C_DIM + 1];

    float freq = expf(-(2.0f * (float)i) * (1.0f / 64.0f) * 9.210340371976184f);
    float th = (float)t * freq;
    float s, c;
    sincosf(th, &s, &c);

    size_t o = ((size_t)(b * H_NUM + h) * T_LEN + t) * DH + 2 * i;
    q[o]   = tf32f((q1 * c - q2 * s) * Q_SCALE);
    q[o+1] = tf32f((q1 * s + q2 * c) * Q_SCALE);
    k[o]   = tf32f(k1 * c - k2 * s);
    k[o+1] = tf32f(k1 * s + k2 * c);
}

// ---------------- V transpose: qkv v-section -> [B,H,dh,T], tf32 ------------
__global__ void vtrans_kernel(const float* __restrict__ qkv,
                              float* __restrict__ vt) {
    __shared__ float s[64][65];
    int bh = blockIdx.y;
    int b  = bh >> 4;
    int h  = bh & 15;
    int t0 = blockIdx.x * 64;
    int tid = threadIdx.x;

    for (int idx = tid; idx < 64 * 64; idx += 256) {
        int tok = idx >> 6, d = idx & 63;
        s[tok][d] = qkv[(size_t)(b * T_LEN + t0 + tok) * (3 * C_DIM)
                        + 2 * C_DIM + h * DH + d];
    }
    __syncthreads();
    for (int idx = tid; idx < 64 * 64; idx += 256) {
        int d = idx >> 6, tok = idx & 63;
        vt[((size_t)bh * DH + d) * T_LEN + t0 + tok] = tf32f(s[tok][d]);
    }
}

// ---------------- tensor-core causal flash attention (R4, proven) -----------
#define APAD 68
__global__ __launch_bounds__(128)
void attn_mma_kernel(const float* __restrict__ Q,
                     const float* __restrict__ Kg,
                     const float* __restrict__ Vt,
                     float* __restrict__ O) {
    extern __shared__ float smf[];
    float* sQ = smf;
    float* sK = smf + 64 * APAD;
    float* sV = smf + 2 * 64 * APAD;

    int bh   = blockIdx.y;
    int b    = bh >> 4;
    int head = bh & 15;
    int q0   = blockIdx.x * 64;
    int tid  = threadIdx.x;
    int warp = tid >> 5;
    int lane = tid & 31;
    int wm   = warp * 16;
    int g    = lane >> 2;
    int t    = lane & 3;
    int i    = lane & 7;
    int sub  = lane >> 3;

    uint32_t smBase = (uint32_t)__cvta_generic_to_shared(smf);
    const uint32_t K_OFF = 64 * APAD * 4;
    const uint32_t V_OFF = 2 * 64 * APAD * 4;

    const float* qg = Q + ((size_t)bh * T_LEN + q0) * DH;
    for (int idx = tid; idx < 64 * 16; idx += 128) {
        int r = idx >> 4, c4 = (idx & 15) * 4;
        *(float4*)&sQ[r * APAD + c4] = *(const float4*)(qg + r * DH + c4);
    }
    __syncthreads();

    uint32_t qf[8][4];
    {
        int row = wm + (sub & 1) * 8 + i;
        #pragma unroll
        for (int kq = 0; kq < 8; kq++) {
            uint32_t off = (uint32_t)(row * APAD + kq * 8 + (sub >> 1) * 4) * 4u;
            ldsm4(qf[kq][0], qf[kq][1], qf[kq][2], qf[kq][3], smBase + off);
        }
    }

    float accO[8][4];
    #pragma unroll
    for (int nt = 0; nt < 8; nt++)
        #pragma unroll
        for (int e = 0; e < 4; e++) accO[nt][e] = 0.f;
    float m0 = -1e30f, m1 = -1e30f, l0 = 0.f, l1 = 0.f;

    int r0 = q0 + wm + g;
    int r1 = r0 + 8;
    int prow0 = (wm + g) * APAD;
    int prow1 = (wm + g + 8) * APAD;
    int arow  = wm + (sub & 1) * 8 + i;

    int ntiles = q0 / 64 + 1;
    for (int kt = 0; kt < ntiles; kt++) {
        int ks = kt * 64;
        const float* kbase = Kg + ((size_t)bh * T_LEN + ks) * DH;
        const float* vbase = Vt + (size_t)bh * DH * T_LEN + ks;
        for (int idx = tid; idx < 64 * 16; idx += 128) {
            int r = idx >> 4, c4 = (idx & 15) * 4;
            *(float4*)&sK[r * APAD + c4] = *(const float4*)(kbase + r * DH + c4);
            *(float4*)&sV[r * APAD + c4] = *(const float4*)(vbase + (size_t)r * T_LEN + c4);
        }
        __syncthreads();

        if (ks <= q0 + wm + 15) {
            float s[8][4];
            #pragma unroll
            for (int nt = 0; nt < 8; nt++)
                #pragma unroll
                for (int e = 0; e < 4; e++) s[nt][e] = 0.f;

            #pragma unroll
            for (int kq = 0; kq < 8; kq++) {
                uint32_t bR[4][4];
                #pragma unroll
                for (int p = 0; p < 4; p++) {
                    int row = p * 16 + (sub >> 1) * 8 + i;
                    uint32_t off = K_OFF +
                        (uint32_t)(row * APAD + kq * 8 + (sub & 1) * 4) * 4u;
                    ldsm4(bR[p][0], bR[p][1], bR[p][2], bR[p][3], smBase + off);
                }
                #pragma unroll
                for (int nt = 0; nt < 8; nt++)
                    mma_tf32(s[nt], qf[kq][0], qf[kq][1], qf[kq][2], qf[kq][3],
                             bR[nt >> 1][(nt & 1) * 2], bR[nt >> 1][(nt & 1) * 2 + 1]);
            }

            if (ks + 63 > q0 + wm) {
                #pragma unroll
                for (int nt = 0; nt < 8; nt++) {
                    int kc = ks + nt * 8 + 2 * t;
                    if (kc     > r0) s[nt][0] = -1e30f;
                    if (kc + 1 > r0) s[nt][1] = -1e30f;
                    if (kc     > r1) s[nt][2] = -1e30f;
                    if (kc + 1 > r1) s[nt][3] = -1e30f;
                }
            }

            float tm0 = -1e30f, tm1 = -1e30f;
            #pragma unroll
            for (int nt = 0; nt < 8; nt++) {
                tm0 = fmaxf(tm0, fmaxf(s[nt][0], s[nt][1]));
                tm1 = fmaxf(tm1, fmaxf(s[nt][2], s[nt][3]));
            }
            tm0 = fmaxf(tm0, __shfl_xor_sync(0xffffffffu, tm0, 1));
            tm0 = fmaxf(tm0, __shfl_xor_sync(0xffffffffu, tm0, 2));
            tm1 = fmaxf(tm1, __shfl_xor_sync(0xffffffffu, tm1, 1));
            tm1 = fmaxf(tm1, __shfl_xor_sync(0xffffffffu, tm1, 2));

            float mn0 = fmaxf(m0, tm0), mn1 = fmaxf(m1, tm1);
            float c0 = exp2f(m0 - mn0), c1 = exp2f(m1 - mn1);

            float ps0 = 0.f, ps1 = 0.f;
            #pragma unroll
            for (int nt = 0; nt < 8; nt++) {
                float2 pa, pb;
                pa.x = exp2f(s[nt][0] - mn0); pa.y = exp2f(s[nt][1] - mn0);
                pb.x = exp2f(s[nt][2] - mn1); pb.y = exp2f(s[nt][3] - mn1);
                ps0 += pa.x + pa.y; ps1 += pb.x + pb.y;
                pa.x = tf32f(pa.x); pa.y = tf32f(pa.y);
                pb.x = tf32f(pb.x); pb.y = tf32f(pb.y);
                int col = nt * 8 + 2 * t;
                *(float2*)&sQ[prow0 + col] = pa;
                *(float2*)&sQ[prow1 + col] = pb;
            }
            ps0 += __shfl_xor_sync(0xffffffffu, ps0, 1);
            ps0 += __shfl_xor_sync(0xffffffffu, ps0, 2);
            ps1 += __shfl_xor_sync(0xffffffffu, ps1, 1);
            ps1 += __shfl_xor_sync(0xffffffffu, ps1, 2);

            l0 = l0 * c0 + ps0;
            l1 = l1 * c1 + ps1;
            m0 = mn0; m1 = mn1;

            #pragma unroll
            for (int nt = 0; nt < 8; nt++) {
                accO[nt][0] *= c0; accO[nt][1] *= c0;
                accO[nt][2] *= c1; accO[nt][3] *= c1;
            }
            __syncwarp();

            #pragma unroll
            for (int kp = 0; kp < 8; kp++) {
                uint32_t aP[4];
                ldsm4(aP[0], aP[1], aP[2], aP[3],
                      smBase + (uint32_t)(arow * APAD + kp * 8 + (sub >> 1) * 4) * 4u);
                uint32_t bV[4][4];
                #pragma unroll
                for (int p = 0; p < 4; p++) {
                    int row = p * 16 + (sub >> 1) * 8 + i;
                    uint32_t off = V_OFF +
                        (uint32_t)(row * APAD + kp * 8 + (sub & 1) * 4) * 4u;
                    ldsm4(bV[p][0], bV[p][1], bV[p][2], bV[p][3], smBase + off);
                }
                #pragma unroll
                for (int nt = 0; nt < 8; nt++)
                    mma_tf32(accO[nt], aP[0], aP[1], aP[2], aP[3],
                             bV[nt >> 1][(nt & 1) * 2], bV[nt >> 1][(nt & 1) * 2 + 1]);
            }
        }
        __syncthreads();
    }

    float inv0 = 1.f / l0, inv1 = 1.f / l1;
    float* o0 = O + ((size_t)(b * T_LEN + r0)) * C_DIM + head * DH;
    float* o1 = O + ((size_t)(b * T_LEN + r1)) * C_DIM + head * DH;
    #pragma unroll
    for (int nt = 0; nt < 8; nt++) {
        int col = nt * 8 + 2 * t;
        float2 v0, v1;
        v0.x = accO[nt][0] * inv0; v0.y = accO[nt][1] * inv0;
        v1.x = accO[nt][2] * inv1; v1.y = accO[nt][3] * inv1;
        *(float2*)(o0 + col) = v0;
        *(float2*)(o1 + col) = v1;
    }
}

// ---------------- launch ----------------------------------------------------
extern "C" void kernel_launch(void* const* d_in, const int* in_sizes, int n_in,
                              void* d_out, int out_size) {
    const float* x      = (const float*)d_in[0];
    const float* w_qkv  = (const float*)d_in[1];
    const float* w_proj = (const float*)d_in[2];
    const float* g1     = (const float*)d_in[3];
    const float* g2     = (const float*)d_in[4];
    const float* w1     = (const float*)d_in[5];
    const float* w2     = (const float*)d_in[6];
    const float* w3     = (const float*)d_in[7];
    float* out = (float*)d_out;

    float *p_h, *p_qkv, *p_q, *p_k, *p_v, *p_o, *p_x1, *p_ff;
    cudaGetSymbolAddress((void**)&p_h,   g_h);
    cudaGetSymbolAddress((void**)&p_qkv, g_qkv);
    cudaGetSymbolAddress((void**)&p_q,   g_q);
    cudaGetSymbolAddress((void**)&p_k,   g_k);
    cudaGetSymbolAddress((void**)&p_v,   g_v);
    cudaGetSymbolAddress((void**)&p_o,   g_o);
    cudaGetSymbolAddress((void**)&p_x1,  g_x1);
    cudaGetSymbolAddress((void**)&p_ff,  g_ff);

    int attn_smem = 3 * 64 * APAD * 4;
    cudaFuncSetAttribute(attn_mma_kernel,
                         cudaFuncAttributeMaxDynamicSharedMemorySize, attn_smem);
    cudaFuncSetAttribute(tgemm_kernel<0>,
                         cudaFuncAttributeMaxDynamicSharedMemorySize, GEMM_SMEM);
    cudaFuncSetAttribute(tgemm_kernel<1>,
                         cudaFuncAttributeMaxDynamicSharedMemorySize, GEMM_SMEM);
    cudaFuncSetAttribute(tgemm_kernel<2>,
                         cudaFuncAttributeMaxDynamicSharedMemorySize, GEMM_SMEM);

    rmsnorm_kernel<<<M_TOK, 256>>>(x, g1, p_h);
    tgemm_kernel<0><<<dim3(3 * C_DIM / 128, M_TOK / 128), 256, GEMM_SMEM>>>(
        p_h, w_qkv, nullptr, p_qkv, M_TOK, 3 * C_DIM, C_DIM);
    rope_split_kernel<<<(M_TOK * H_NUM * 32) / 256, 256>>>(p_qkv, p_q, p_k);
    vtrans_kernel<<<dim3(T_LEN / 64, B_NUM * H_NUM), 256>>>(p_qkv, p_v);
    attn_mma_kernel<<<dim3(T_LEN / 64, B_NUM * H_NUM), 128, attn_smem>>>(
        p_q, p_k, p_v, p_o);
    tgemm_kernel<1><<<dim3(C_DIM / 128, M_TOK / 128), 256, GEMM_SMEM>>>(
        p_o, w_proj, x, p_x1, M_TOK, C_DIM, C_DIM);
    rmsnorm_kernel<<<M_TOK, 256>>>(p_x1, g2, p_h);
    tgemm_kernel<0><<<dim3(FF_DIM / 128, M_TOK / 128), 256, GEMM_SMEM>>>(
        p_h, w1, nullptr, p_ff, M_TOK, FF_DIM, C_DIM);
    tgemm_kernel<2><<<dim3(FF_DIM / 128, M_TOK / 128), 256, GEMM_SMEM>>>(
        p_h, w3, p_ff, p_ff, M_TOK, FF_DIM, C_DIM);
    tgemm_kernel<1><<<dim3(C_DIM / 128, M_TOK / 128), 256, GEMM_SMEM>>>(
        p_ff, w2, p_x1, out, M_TOK, C_DIM, FF_DIM);
}

// round 7
// speedup vs baseline: 1.4026x; 1.4026x over previous
#include <cuda_runtime.h>
#include <cuda_fp16.h>
#include <math.h>
#include <stdint.h>

#define C_DIM   1024
#define H_NUM   16
#define DH      64
#define FF_DIM  4096
#define B_NUM   2
#define T_LEN   2048
#define M_TOK   4096   // B*T

// ---------------- scratch (device globals; no allocation allowed) ----------
__device__ float g_h  [M_TOK * C_DIM];
__device__ float g_qkv[M_TOK * 3 * C_DIM];
__device__ float g_q  [M_TOK * C_DIM];        // [B,H,T,dh]  (pre-scaled, tf32)
__device__ float g_k  [M_TOK * C_DIM];        // [B,H,T,dh]  (tf32)
__device__ float g_v  [M_TOK * C_DIM];        // [B,H,dh,T]  (transposed, tf32)
__device__ float g_o  [M_TOK * C_DIM];        // attention out, [B,T,H*dh]
__device__ float g_x1 [M_TOK * C_DIM];
__device__ float g_ff [M_TOK * FF_DIM];

// ---------------- helpers ----------------------------------------------------
__device__ __forceinline__ uint32_t f2tf32(float x) {
    uint32_t r;
    asm("cvt.rna.tf32.f32 %0, %1;" : "=r"(r) : "f"(x));
    return r;
}
__device__ __forceinline__ float tf32f(float x) { return __uint_as_float(f2tf32(x)); }

__device__ __forceinline__ void mma_tf32(float c[4],
                                         uint32_t a0, uint32_t a1, uint32_t a2, uint32_t a3,
                                         uint32_t b0, uint32_t b1) {
    asm volatile(
        "mma.sync.aligned.m16n8k8.row.col.f32.tf32.tf32.f32 "
        "{%0,%1,%2,%3}, {%4,%5,%6,%7}, {%8,%9}, {%0,%1,%2,%3};\n"
        : "+f"(c[0]), "+f"(c[1]), "+f"(c[2]), "+f"(c[3])
        : "r"(a0), "r"(a1), "r"(a2), "r"(a3), "r"(b0), "r"(b1));
}
__device__ __forceinline__ void mma_f16(float c[4],
                                        uint32_t a0, uint32_t a1, uint32_t a2, uint32_t a3,
                                        uint32_t b0, uint32_t b1) {
    asm volatile(
        "mma.sync.aligned.m16n8k16.row.col.f32.f16.f16.f32 "
        "{%0,%1,%2,%3}, {%4,%5,%6,%7}, {%8,%9}, {%0,%1,%2,%3};\n"
        : "+f"(c[0]), "+f"(c[1]), "+f"(c[2]), "+f"(c[3])
        : "r"(a0), "r"(a1), "r"(a2), "r"(a3), "r"(b0), "r"(b1));
}
__device__ __forceinline__ void ldsm4(uint32_t& r0, uint32_t& r1,
                                      uint32_t& r2, uint32_t& r3, uint32_t addr) {
    asm volatile("ldmatrix.sync.aligned.m8n8.x4.shared.b16 {%0,%1,%2,%3}, [%4];"
                 : "=r"(r0), "=r"(r1), "=r"(r2), "=r"(r3) : "r"(addr));
}
__device__ __forceinline__ uint4 pack8h(float4 a, float4 b) {
    __half2 h0 = __floats2half2_rn(a.x, a.y);
    __half2 h1 = __floats2half2_rn(a.z, a.w);
    __half2 h2 = __floats2half2_rn(b.x, b.y);
    __half2 h3 = __floats2half2_rn(b.z, b.w);
    uint4 u;
    u.x = *(uint32_t*)&h0; u.y = *(uint32_t*)&h1;
    u.z = *(uint32_t*)&h2; u.w = *(uint32_t*)&h3;
    return u;
}

// ---------------- RMSNorm ----------------------------------------------------
__global__ void rmsnorm_kernel(const float* __restrict__ x,
                               const float* __restrict__ g,
                               float* __restrict__ y) {
    int row = blockIdx.x;
    int tid = threadIdx.x;
    const float4* xr = (const float4*)(x + (size_t)row * C_DIM);
    const float4* gr = (const float4*)g;
    float4*       yr = (float4*)(y + (size_t)row * C_DIM);

    float4 xv = xr[tid];
    float ss = xv.x*xv.x + xv.y*xv.y + xv.z*xv.z + xv.w*xv.w;
    #pragma unroll
    for (int off = 16; off > 0; off >>= 1)
        ss += __shfl_xor_sync(0xffffffffu, ss, off);
    __shared__ float red[8];
    if ((tid & 31) == 0) red[tid >> 5] = ss;
    __syncthreads();
    float tot = 0.f;
    #pragma unroll
    for (int i = 0; i < 8; i++) tot += red[i];
    float inv = rsqrtf(tot * (1.0f / C_DIM) + 1e-5f);

    float4 gv = gr[tid];
    float4 o;
    o.x = xv.x * gv.x * inv;
    o.y = xv.y * gv.y * inv;
    o.z = xv.z * gv.z * inv;
    o.w = xv.w * gv.w * inv;
    yr[tid] = o;
}

// ---------------- fp16 tensor-core GEMM: C[M,N] = A[M,K] @ W[N,K]^T ---------
// Block 128x128, BK=16, double-buffered, register prefetch (R4 skeleton).
// 8 warps (4m x 2n), warp tile 32x64. A m16k16 + B n8k16 via ldmatrix.x4.
// smem row = 16 halves (32B), XOR swizzle on 16B units.
// MODE 0: plain  MODE 1: +X residual  MODE 2: silu(X) * acc
template <int MODE>
__global__ __launch_bounds__(256, 2)
void hgemm_kernel(const float* __restrict__ A, const float* __restrict__ W,
                  const float* X, float* Cout, int M, int N, int K) {
    __shared__ __align__(16) __half sA[2][128 * 16];
    __shared__ __align__(16) __half sB[2][128 * 16];

    int tid  = threadIdx.x;
    int bm   = blockIdx.y * 128;
    int bn   = blockIdx.x * 128;
    int warp = tid >> 5;
    int lane = tid & 31;
    int wm   = (warp >> 1) * 32;
    int wn   = (warp & 1) * 64;

    // global load / smem store mapping: row = tid>>1, k-octet hf = tid&1
    int lr = tid >> 1;
    int hf = tid & 1;
    const float* Aptr = A + (size_t)(bm + lr) * K + hf * 8;
    const float* Wptr = W + (size_t)(bn + lr) * K + hf * 8;
    int sidx = lr * 16 + (hf ^ ((lr >> 2) & 1)) * 8;   // half index (16B unit)

    uint32_t aBase = (uint32_t)__cvta_generic_to_shared(&sA[0][0]);
    uint32_t bBase = (uint32_t)__cvta_generic_to_shared(&sB[0][0]);

    // ldmatrix offsets
    int l15 = lane & 15, lh = lane >> 4;
    uint32_t offA[2];
    #pragma unroll
    for (int mt = 0; mt < 2; mt++) {
        int row = wm + mt * 16 + l15;
        int u   = lh ^ ((row >> 2) & 1);
        offA[mt] = (uint32_t)(row * 16 + u * 8) * 2u;
    }
    uint32_t offB[2][2];   // [k-octet][n-group of 32]
    #pragma unroll
    for (int kh = 0; kh < 2; kh++)
        #pragma unroll
        for (int gb = 0; gb < 2; gb++) {
            int row = wn + gb * 32 + lane;
            int u   = kh ^ ((row >> 2) & 1);
            offB[kh][gb] = (uint32_t)(row * 16 + u * 8) * 2u;
        }

    float acc[2][8][4];
    #pragma unroll
    for (int mt = 0; mt < 2; mt++)
        #pragma unroll
        for (int nt = 0; nt < 8; nt++)
            #pragma unroll
            for (int e = 0; e < 4; e++) acc[mt][nt][e] = 0.f;

    // prologue: stage 0 (k 0..15)
    {
        float4 a0 = *(const float4*)(Aptr);
        float4 a1 = *(const float4*)(Aptr + 4);
        float4 b0 = *(const float4*)(Wptr);
        float4 b1 = *(const float4*)(Wptr + 4);
        *(uint4*)&sA[0][sidx] = pack8h(a0, a1);
        *(uint4*)&sB[0][sidx] = pack8h(b0, b1);
    }
    __syncthreads();

    int NC = K >> 4;
    int st = 0;
    for (int ck = 0; ck < NC; ck++) {
        bool more = (ck + 1) < NC;
        float4 na0, na1, nb0, nb1;
        if (more) {
            na0 = *(const float4*)(Aptr + (ck + 1) * 16);
            na1 = *(const float4*)(Aptr + (ck + 1) * 16 + 4);
            nb0 = *(const float4*)(Wptr + (ck + 1) * 16);
            nb1 = *(const float4*)(Wptr + (ck + 1) * 16 + 4);
        }

        uint32_t tA = aBase + st * (128 * 16 * 2);
        uint32_t tB = bBase + st * (128 * 16 * 2);
        uint32_t aR[2][4], bR[2][2][4];
        ldsm4(aR[0][0], aR[0][1], aR[0][2], aR[0][3], tA + offA[0]);
        ldsm4(aR[1][0], aR[1][1], aR[1][2], aR[1][3], tA + offA[1]);
        #pragma unroll
        for (int kh = 0; kh < 2; kh++)
            #pragma unroll
            for (int gb = 0; gb < 2; gb++)
                ldsm4(bR[kh][gb][0], bR[kh][gb][1], bR[kh][gb][2], bR[kh][gb][3],
                      tB + offB[kh][gb]);

        #pragma unroll
        for (int mt = 0; mt < 2; mt++)
            #pragma unroll
            for (int nt = 0; nt < 8; nt++)
                mma_f16(acc[mt][nt],
                        aR[mt][0], aR[mt][1], aR[mt][2], aR[mt][3],
                        bR[0][nt >> 2][nt & 3], bR[1][nt >> 2][nt & 3]);

        if (more) {
            *(uint4*)&sA[st ^ 1][sidx] = pack8h(na0, na1);
            *(uint4*)&sB[st ^ 1][sidx] = pack8h(nb0, nb1);
        }
        __syncthreads();
        st ^= 1;
    }

    // epilogue: row = bm+wm+mt*16+half*8+g ; col = bn+wn+nt*8+2t
    int g = lane >> 2;
    int t = lane & 3;
    #pragma unroll
    for (int mt = 0; mt < 2; mt++) {
        #pragma unroll
        for (int half = 0; half < 2; half++) {
            int row = bm + wm + mt * 16 + half * 8 + g;
            float*       crow = Cout + (size_t)row * N;
            const float* xrow = (MODE != 0) ? (X + (size_t)row * N) : nullptr;
            #pragma unroll
            for (int nt = 0; nt < 8; nt++) {
                int col = bn + wn + nt * 8 + 2 * t;
                float2 v;
                v.x = acc[mt][nt][half * 2 + 0];
                v.y = acc[mt][nt][half * 2 + 1];
                if (MODE == 1) {
                    float2 xv = *(const float2*)(xrow + col);
                    v.x += xv.x; v.y += xv.y;
                }
                if (MODE == 2) {
                    float2 xv = *(const float2*)(xrow + col);
                    v.x *= xv.x / (1.f + expf(-xv.x));
                    v.y *= xv.y / (1.f + expf(-xv.y));
                }
                *(float2*)(crow + col) = v;
            }
        }
    }
}

// ---------------- RoPE + split qkv -> q,k in [B,H,T,dh] (tf32, q pre-scaled)
#define Q_SCALE (0.125f * 1.44269504088896f)   // 1/sqrt(64) * log2(e)
__global__ void rope_split_kernel(const float* __restrict__ qkv,
                                  float* __restrict__ q,
                                  float* __restrict__ k) {
    int idx = blockIdx.x * blockDim.x + threadIdx.x;
    int i = idx & 31;
    int h = (idx >> 5) & 15;
    int m = idx >> 9;
    int b = m >> 11;
    int t = m & 2047;

    const float* base = qkv + (size_t)m * (3 * C_DIM) + h * DH + 2 * i;
    float q1 = base[0],     q2 = base[1];
    float k1 = base[C_DIM], k2 = base[C_DIM + 1];

    float freq = expf(-(2.0f * (float)i) * (1.0f / 64.0f) * 9.210340371976184f);
    float th = (float)t * freq;
    float s, c;
    sincosf(th, &s, &c);

    size_t o = ((size_t)(b * H_NUM + h) * T_LEN + t) * DH + 2 * i;
    q[o]   = tf32f((q1 * c - q2 * s) * Q_SCALE);
    q[o+1] = tf32f((q1 * s + q2 * c) * Q_SCALE);
    k[o]   = tf32f(k1 * c - k2 * s);
    k[o+1] = tf32f(k1 * s + k2 * c);
}

// ---------------- V transpose: qkv v-section -> [B,H,dh,T], tf32 ------------
__global__ void vtrans_kernel(const float* __restrict__ qkv,
                              float* __restrict__ vt) {
    __shared__ float s[64][65];
    int bh = blockIdx.y;
    int b  = bh >> 4;
    int h  = bh & 15;
    int t0 = blockIdx.x * 64;
    int tid = threadIdx.x;

    for (int idx = tid; idx < 64 * 64; idx += 256) {
        int tok = idx >> 6, d = idx & 63;
        s[tok][d] = qkv[(size_t)(b * T_LEN + t0 + tok) * (3 * C_DIM)
                        + 2 * C_DIM + h * DH + d];
    }
    __syncthreads();
    for (int idx = tid; idx < 64 * 64; idx += 256) {
        int d = idx >> 6, tok = idx & 63;
        vt[((size_t)bh * DH + d) * T_LEN + t0 + tok] = tf32f(s[tok][d]);
    }
}

// ---------------- tensor-core causal flash attention (R4, proven) -----------
#define APAD 68
__global__ __launch_bounds__(128)
void attn_mma_kernel(const float* __restrict__ Q,
                     const float* __restrict__ Kg,
                     const float* __restrict__ Vt,
                     float* __restrict__ O) {
    extern __shared__ float smf[];
    float* sQ = smf;
    float* sK = smf + 64 * APAD;
    float* sV = smf + 2 * 64 * APAD;

    int bh   = blockIdx.y;
    int b    = bh >> 4;
    int head = bh & 15;
    int q0   = blockIdx.x * 64;
    int tid  = threadIdx.x;
    int warp = tid >> 5;
    int lane = tid & 31;
    int wm   = warp * 16;
    int g    = lane >> 2;
    int t    = lane & 3;
    int i    = lane & 7;
    int sub  = lane >> 3;

    uint32_t smBase = (uint32_t)__cvta_generic_to_shared(smf);
    const uint32_t K_OFF = 64 * APAD * 4;
    const uint32_t V_OFF = 2 * 64 * APAD * 4;

    const float* qg = Q + ((size_t)bh * T_LEN + q0) * DH;
    for (int idx = tid; idx < 64 * 16; idx += 128) {
        int r = idx >> 4, c4 = (idx & 15) * 4;
        *(float4*)&sQ[r * APAD + c4] = *(const float4*)(qg + r * DH + c4);
    }
    __syncthreads();

    uint32_t qf[8][4];
    {
        int row = wm + (sub & 1) * 8 + i;
        #pragma unroll
        for (int kq = 0; kq < 8; kq++) {
            uint32_t off = (uint32_t)(row * APAD + kq * 8 + (sub >> 1) * 4) * 4u;
            ldsm4(qf[kq][0], qf[kq][1], qf[kq][2], qf[kq][3], smBase + off);
        }
    }

    float accO[8][4];
    #pragma unroll
    for (int nt = 0; nt < 8; nt++)
        #pragma unroll
        for (int e = 0; e < 4; e++) accO[nt][e] = 0.f;
    float m0 = -1e30f, m1 = -1e30f, l0 = 0.f, l1 = 0.f;

    int r0 = q0 + wm + g;
    int r1 = r0 + 8;
    int prow0 = (wm + g) * APAD;
    int prow1 = (wm + g + 8) * APAD;
    int arow  = wm + (sub & 1) * 8 + i;

    int ntiles = q0 / 64 + 1;
    for (int kt = 0; kt < ntiles; kt++) {
        int ks = kt * 64;
        const float* kbase = Kg + ((size_t)bh * T_LEN + ks) * DH;
        const float* vbase = Vt + (size_t)bh * DH * T_LEN + ks;
        for (int idx = tid; idx < 64 * 16; idx += 128) {
            int r = idx >> 4, c4 = (idx & 15) * 4;
            *(float4*)&sK[r * APAD + c4] = *(const float4*)(kbase + r * DH + c4);
            *(float4*)&sV[r * APAD + c4] = *(const float4*)(vbase + (size_t)r * T_LEN + c4);
        }
        __syncthreads();

        if (ks <= q0 + wm + 15) {
            float s[8][4];
            #pragma unroll
            for (int nt = 0; nt < 8; nt++)
                #pragma unroll
                for (int e = 0; e < 4; e++) s[nt][e] = 0.f;

            #pragma unroll
            for (int kq = 0; kq < 8; kq++) {
                uint32_t bR[4][4];
                #pragma unroll
                for (int p = 0; p < 4; p++) {
                    int row = p * 16 + (sub >> 1) * 8 + i;
                    uint32_t off = K_OFF +
                        (uint32_t)(row * APAD + kq * 8 + (sub & 1) * 4) * 4u;
                    ldsm4(bR[p][0], bR[p][1], bR[p][2], bR[p][3], smBase + off);
                }
                #pragma unroll
                for (int nt = 0; nt < 8; nt++)
                    mma_tf32(s[nt], qf[kq][0], qf[kq][1], qf[kq][2], qf[kq][3],
                             bR[nt >> 1][(nt & 1) * 2], bR[nt >> 1][(nt & 1) * 2 + 1]);
            }

            if (ks + 63 > q0 + wm) {
                #pragma unroll
                for (int nt = 0; nt < 8; nt++) {
                    int kc = ks + nt * 8 + 2 * t;
                    if (kc     > r0) s[nt][0] = -1e30f;
                    if (kc + 1 > r0) s[nt][1] = -1e30f;
                    if (kc     > r1) s[nt][2] = -1e30f;
                    if (kc + 1 > r1) s[nt][3] = -1e30f;
                }
            }

            float tm0 = -1e30f, tm1 = -1e30f;
            #pragma unroll
            for (int nt = 0; nt < 8; nt++) {
                tm0 = fmaxf(tm0, fmaxf(s[nt][0], s[nt][1]));
                tm1 = fmaxf(tm1, fmaxf(s[nt][2], s[nt][3]));
            }
            tm0 = fmaxf(tm0, __shfl_xor_sync(0xffffffffu, tm0, 1));
            tm0 = fmaxf(tm0, __shfl_xor_sync(0xffffffffu, tm0, 2));
            tm1 = fmaxf(tm1, __shfl_xor_sync(0xffffffffu, tm1, 1));
            tm1 = fmaxf(tm1, __shfl_xor_sync(0xffffffffu, tm1, 2));

            float mn0 = fmaxf(m0, tm0), mn1 = fmaxf(m1, tm1);
            float c0 = exp2f(m0 - mn0), c1 = exp2f(m1 - mn1);

            float ps0 = 0.f, ps1 = 0.f;
            #pragma unroll
            for (int nt = 0; nt < 8; nt++) {
                float2 pa, pb;
                pa.x = exp2f(s[nt][0] - mn0); pa.y = exp2f(s[nt][1] - mn0);
                pb.x = exp2f(s[nt][2] - mn1); pb.y = exp2f(s[nt][3] - mn1);
                ps0 += pa.x + pa.y; ps1 += pb.x + pb.y;
                pa.x = tf32f(pa.x); pa.y = tf32f(pa.y);
                pb.x = tf32f(pb.x); pb.y = tf32f(pb.y);
                int col = nt * 8 + 2 * t;
                *(float2*)&sQ[prow0 + col] = pa;
                *(float2*)&sQ[prow1 + col] = pb;
            }
            ps0 += __shfl_xor_sync(0xffffffffu, ps0, 1);
            ps0 += __shfl_xor_sync(0xffffffffu, ps0, 2);
            ps1 += __shfl_xor_sync(0xffffffffu, ps1, 1);
            ps1 += __shfl_xor_sync(0xffffffffu, ps1, 2);

            l0 = l0 * c0 + ps0;
            l1 = l1 * c1 + ps1;
            m0 = mn0; m1 = mn1;

            #pragma unroll
            for (int nt = 0; nt < 8; nt++) {
                accO[nt][0] *= c0; accO[nt][1] *= c0;
                accO[nt][2] *= c1; accO[nt][3] *= c1;
            }
            __syncwarp();

            #pragma unroll
            for (int kp = 0; kp < 8; kp++) {
                uint32_t aP[4];
                ldsm4(aP[0], aP[1], aP[2], aP[3],
                      smBase + (uint32_t)(arow * APAD + kp * 8 + (sub >> 1) * 4) * 4u);
                uint32_t bV[4][4];
                #pragma unroll
                for (int p = 0; p < 4; p++) {
                    int row = p * 16 + (sub >> 1) * 8 + i;
                    uint32_t off = V_OFF +
                        (uint32_t)(row * APAD + kp * 8 + (sub & 1) * 4) * 4u;
                    ldsm4(bV[p][0], bV[p][1], bV[p][2], bV[p][3], smBase + off);
                }
                #pragma unroll
                for (int nt = 0; nt < 8; nt++)
                    mma_tf32(accO[nt], aP[0], aP[1], aP[2], aP[3],
                             bV[nt >> 1][(nt & 1) * 2], bV[nt >> 1][(nt & 1) * 2 + 1]);
            }
        }
        __syncthreads();
    }

    float inv0 = 1.f / l0, inv1 = 1.f / l1;
    float* o0 = O + ((size_t)(b * T_LEN + r0)) * C_DIM + head * DH;
    float* o1 = O + ((size_t)(b * T_LEN + r1)) * C_DIM + head * DH;
    #pragma unroll
    for (int nt = 0; nt < 8; nt++) {
        int col = nt * 8 + 2 * t;
        float2 v0, v1;
        v0.x = accO[nt][0] * inv0; v0.y = accO[nt][1] * inv0;
        v1.x = accO[nt][2] * inv1; v1.y = accO[nt][3] * inv1;
        *(float2*)(o0 + col) = v0;
        *(float2*)(o1 + col) = v1;
    }
}

// ---------------- launch ----------------------------------------------------
extern "C" void kernel_launch(void* const* d_in, const int* in_sizes, int n_in,
                              void* d_out, int out_size) {
    const float* x      = (const float*)d_in[0];
    const float* w_qkv  = (const float*)d_in[1];
    const float* w_proj = (const float*)d_in[2];
    const float* g1     = (const float*)d_in[3];
    const float* g2     = (const float*)d_in[4];
    const float* w1     = (const float*)d_in[5];
    const float* w2     = (const float*)d_in[6];
    const float* w3     = (const float*)d_in[7];
    float* out = (float*)d_out;

    float *p_h, *p_qkv, *p_q, *p_k, *p_v, *p_o, *p_x1, *p_ff;
    cudaGetSymbolAddress((void**)&p_h,   g_h);
    cudaGetSymbolAddress((void**)&p_qkv, g_qkv);
    cudaGetSymbolAddress((void**)&p_q,   g_q);
    cudaGetSymbolAddress((void**)&p_k,   g_k);
    cudaGetSymbolAddress((void**)&p_v,   g_v);
    cudaGetSymbolAddress((void**)&p_o,   g_o);
    cudaGetSymbolAddress((void**)&p_x1,  g_x1);
    cudaGetSymbolAddress((void**)&p_ff,  g_ff);

    int attn_smem = 3 * 64 * APAD * 4;
    cudaFuncSetAttribute(attn_mma_kernel,
                         cudaFuncAttributeMaxDynamicSharedMemorySize, attn_smem);

    rmsnorm_kernel<<<M_TOK, 256>>>(x, g1, p_h);
    hgemm_kernel<0><<<dim3(3 * C_DIM / 128, M_TOK / 128), 256>>>(
        p_h, w_qkv, nullptr, p_qkv, M_TOK, 3 * C_DIM, C_DIM);
    rope_split_kernel<<<(M_TOK * H_NUM * 32) / 256, 256>>>(p_qkv, p_q, p_k);
    vtrans_kernel<<<dim3(T_LEN / 64, B_NUM * H_NUM), 256>>>(p_qkv, p_v);
    attn_mma_kernel<<<dim3(T_LEN / 64, B_NUM * H_NUM), 128, attn_smem>>>(
        p_q, p_k, p_v, p_o);
    hgemm_kernel<1><<<dim3(C_DIM / 128, M_TOK / 128), 256>>>(
        p_o, w_proj, x, p_x1, M_TOK, C_DIM, C_DIM);
    rmsnorm_kernel<<<M_TOK, 256>>>(p_x1, g2, p_h);
    hgemm_kernel<0><<<dim3(FF_DIM / 128, M_TOK / 128), 256>>>(
        p_h, w1, nullptr, p_ff, M_TOK, FF_DIM, C_DIM);
    hgemm_kernel<2><<<dim3(FF_DIM / 128, M_TOK / 128), 256>>>(
        p_h, w3, p_ff, p_ff, M_TOK, FF_DIM, C_DIM);
    hgemm_kernel<1><<<dim3(C_DIM / 128, M_TOK / 128), 256>>>(
        p_ff, w2, p_x1, out, M_TOK, C_DIM, FF_DIM);
}

// round 8
// speedup vs baseline: 1.7796x; 1.2688x over previous
#include <cuda_runtime.h>
#include <cuda_fp16.h>
#include <math.h>
#include <stdint.h>

#define C_DIM   1024
#define H_NUM   16
#define DH      64
#define FF_DIM  4096
#define B_NUM   2
#define T_LEN   2048
#define M_TOK   4096   // B*T

// ---------------- scratch (device globals; no allocation allowed) ----------
__device__ __half g_h16 [M_TOK * C_DIM];       // rmsnorm out (fp16)
__device__ float  g_qkv [M_TOK * 3 * C_DIM];
__device__ float  g_q   [M_TOK * C_DIM];       // [B,H,T,dh] (pre-scaled, tf32)
__device__ float  g_k   [M_TOK * C_DIM];       // [B,H,T,dh] (tf32)
__device__ float  g_v   [M_TOK * C_DIM];       // [B,H,dh,T] (transposed, tf32)
__device__ __half g_o16 [M_TOK * C_DIM];       // attention out (fp16)
__device__ float  g_x1  [M_TOK * C_DIM];
__device__ float  g_ff  [M_TOK * FF_DIM];      // a = h2 @ w1^T (fp32)
__device__ __half g_ff16[M_TOK * FF_DIM];      // silu(a)*b (fp16)
__device__ __half g_w16 [(3 + 1 + 4 + 4 + 4) * C_DIM * C_DIM];  // all weights fp16

// ---------------- helpers ----------------------------------------------------
__device__ __forceinline__ uint32_t f2tf32(float x) {
    uint32_t r;
    asm("cvt.rna.tf32.f32 %0, %1;" : "=r"(r) : "f"(x));
    return r;
}
__device__ __forceinline__ float tf32f(float x) { return __uint_as_float(f2tf32(x)); }

__device__ __forceinline__ void mma_tf32(float c[4],
                                         uint32_t a0, uint32_t a1, uint32_t a2, uint32_t a3,
                                         uint32_t b0, uint32_t b1) {
    asm volatile(
        "mma.sync.aligned.m16n8k8.row.col.f32.tf32.tf32.f32 "
        "{%0,%1,%2,%3}, {%4,%5,%6,%7}, {%8,%9}, {%0,%1,%2,%3};\n"
        : "+f"(c[0]), "+f"(c[1]), "+f"(c[2]), "+f"(c[3])
        : "r"(a0), "r"(a1), "r"(a2), "r"(a3), "r"(b0), "r"(b1));
}
__device__ __forceinline__ void mma_f16(float c[4],
                                        uint32_t a0, uint32_t a1, uint32_t a2, uint32_t a3,
                                        uint32_t b0, uint32_t b1) {
    asm volatile(
        "mma.sync.aligned.m16n8k16.row.col.f32.f16.f16.f32 "
        "{%0,%1,%2,%3}, {%4,%5,%6,%7}, {%8,%9}, {%0,%1,%2,%3};\n"
        : "+f"(c[0]), "+f"(c[1]), "+f"(c[2]), "+f"(c[3])
        : "r"(a0), "r"(a1), "r"(a2), "r"(a3), "r"(b0), "r"(b1));
}
__device__ __forceinline__ void ldsm4(uint32_t& r0, uint32_t& r1,
                                      uint32_t& r2, uint32_t& r3, uint32_t addr) {
    asm volatile("ldmatrix.sync.aligned.m8n8.x4.shared.b16 {%0,%1,%2,%3}, [%4];"
                 : "=r"(r0), "=r"(r1), "=r"(r2), "=r"(r3) : "r"(addr));
}

// ---------------- fp32 -> fp16 convert (8 elems/thread) ---------------------
__global__ void f2h_kernel(const float* __restrict__ in, __half* __restrict__ out) {
    int idx = (blockIdx.x * blockDim.x + threadIdx.x) * 8;
    float4 a = *(const float4*)(in + idx);
    float4 b = *(const float4*)(in + idx + 4);
    __half2 h0 = __floats2half2_rn(a.x, a.y);
    __half2 h1 = __floats2half2_rn(a.z, a.w);
    __half2 h2 = __floats2half2_rn(b.x, b.y);
    __half2 h3 = __floats2half2_rn(b.z, b.w);
    uint4 u;
    u.x = *(uint32_t*)&h0; u.y = *(uint32_t*)&h1;
    u.z = *(uint32_t*)&h2; u.w = *(uint32_t*)&h3;
    *(uint4*)(out + idx) = u;
}

// ---------------- RMSNorm -> fp16 --------------------------------------------
__global__ void rmsnorm_h_kernel(const float* __restrict__ x,
                                 const float* __restrict__ g,
                                 __half* __restrict__ y) {
    int row = blockIdx.x;
    int tid = threadIdx.x;
    const float4* xr = (const float4*)(x + (size_t)row * C_DIM);
    const float4* gr = (const float4*)g;

    float4 xv = xr[tid];
    float ss = xv.x*xv.x + xv.y*xv.y + xv.z*xv.z + xv.w*xv.w;
    #pragma unroll
    for (int off = 16; off > 0; off >>= 1)
        ss += __shfl_xor_sync(0xffffffffu, ss, off);
    __shared__ float red[8];
    if ((tid & 31) == 0) red[tid >> 5] = ss;
    __syncthreads();
    float tot = 0.f;
    #pragma unroll
    for (int i = 0; i < 8; i++) tot += red[i];
    float inv = rsqrtf(tot * (1.0f / C_DIM) + 1e-5f);

    float4 gv = gr[tid];
    __half2 h0 = __floats2half2_rn(xv.x * gv.x * inv, xv.y * gv.y * inv);
    __half2 h1 = __floats2half2_rn(xv.z * gv.z * inv, xv.w * gv.w * inv);
    uint2 u;
    u.x = *(uint32_t*)&h0; u.y = *(uint32_t*)&h1;
    *(uint2*)(y + (size_t)row * C_DIM + tid * 4) = u;
}

// ---------------- fp16 tensor-core GEMM: C[M,N] = A[M,K] @ W[N,K]^T ---------
// A, W in fp16 (pre-converted). Block 128x128, BK=16, double-buffered,
// register prefetch. 8 warps (4m x 2n), warp tile 32x64.
// MODE 0: fp32 out  MODE 1: fp32 out + X residual  MODE 2: fp16 out, silu(X)*acc
template <int MODE>
__global__ __launch_bounds__(256, 2)
void hgemm_kernel(const __half* __restrict__ A, const __half* __restrict__ W,
                  const float* X, void* Cout, int M, int N, int K) {
    __shared__ __align__(16) __half sA[2][128 * 16];
    __shared__ __align__(16) __half sB[2][128 * 16];

    int tid  = threadIdx.x;
    int bm   = blockIdx.y * 128;
    int bn   = blockIdx.x * 128;
    int warp = tid >> 5;
    int lane = tid & 31;
    int wm   = (warp >> 1) * 32;
    int wn   = (warp & 1) * 64;

    // global load / smem store mapping: row = tid>>1, k-octet hf = tid&1
    int lr = tid >> 1;
    int hf = tid & 1;
    const __half* Aptr = A + (size_t)(bm + lr) * K + hf * 8;
    const __half* Wptr = W + (size_t)(bn + lr) * K + hf * 8;
    int sidx = lr * 16 + (hf ^ ((lr >> 2) & 1)) * 8;   // half index (16B unit)

    uint32_t aBase = (uint32_t)__cvta_generic_to_shared(&sA[0][0]);
    uint32_t bBase = (uint32_t)__cvta_generic_to_shared(&sB[0][0]);

    // ldmatrix offsets
    int l15 = lane & 15, lh = lane >> 4;
    uint32_t offA[2];
    #pragma unroll
    for (int mt = 0; mt < 2; mt++) {
        int row = wm + mt * 16 + l15;
        int u   = lh ^ ((row >> 2) & 1);
        offA[mt] = (uint32_t)(row * 16 + u * 8) * 2u;
    }
    uint32_t offB[2][2];   // [k-octet][n-group of 32]
    #pragma unroll
    for (int kh = 0; kh < 2; kh++)
        #pragma unroll
        for (int gb = 0; gb < 2; gb++) {
            int row = wn + gb * 32 + lane;
            int u   = kh ^ ((row >> 2) & 1);
            offB[kh][gb] = (uint32_t)(row * 16 + u * 8) * 2u;
        }

    float acc[2][8][4];
    #pragma unroll
    for (int mt = 0; mt < 2; mt++)
        #pragma unroll
        for (int nt = 0; nt < 8; nt++)
            #pragma unroll
            for (int e = 0; e < 4; e++) acc[mt][nt][e] = 0.f;

    // prologue: stage 0
    *(uint4*)&sA[0][sidx] = *(const uint4*)(Aptr);
    *(uint4*)&sB[0][sidx] = *(const uint4*)(Wptr);
    __syncthreads();

    int NC = K >> 4;
    int st = 0;
    for (int ck = 0; ck < NC; ck++) {
        bool more = (ck + 1) < NC;
        uint4 na, nb;
        if (more) {
            na = *(const uint4*)(Aptr + (ck + 1) * 16);
            nb = *(const uint4*)(Wptr + (ck + 1) * 16);
        }

        uint32_t tA = aBase + st * (128 * 16 * 2);
        uint32_t tB = bBase + st * (128 * 16 * 2);
        uint32_t aR[2][4], bR[2][2][4];
        ldsm4(aR[0][0], aR[0][1], aR[0][2], aR[0][3], tA + offA[0]);
        ldsm4(aR[1][0], aR[1][1], aR[1][2], aR[1][3], tA + offA[1]);
        #pragma unroll
        for (int kh = 0; kh < 2; kh++)
            #pragma unroll
            for (int gb = 0; gb < 2; gb++)
                ldsm4(bR[kh][gb][0], bR[kh][gb][1], bR[kh][gb][2], bR[kh][gb][3],
                      tB + offB[kh][gb]);

        #pragma unroll
        for (int mt = 0; mt < 2; mt++)
            #pragma unroll
            for (int nt = 0; nt < 8; nt++)
                mma_f16(acc[mt][nt],
                        aR[mt][0], aR[mt][1], aR[mt][2], aR[mt][3],
                        bR[0][nt >> 2][nt & 3], bR[1][nt >> 2][nt & 3]);

        if (more) {
            *(uint4*)&sA[st ^ 1][sidx] = na;
            *(uint4*)&sB[st ^ 1][sidx] = nb;
        }
        __syncthreads();
        st ^= 1;
    }

    // epilogue
    int g = lane >> 2;
    int t = lane & 3;
    #pragma unroll
    for (int mt = 0; mt < 2; mt++) {
        #pragma unroll
        for (int half = 0; half < 2; half++) {
            int row = bm + wm + mt * 16 + half * 8 + g;
            const float* xrow = (MODE != 0) ? (X + (size_t)row * N) : nullptr;
            #pragma unroll
            for (int nt = 0; nt < 8; nt++) {
                int col = bn + wn + nt * 8 + 2 * t;
                float2 v;
                v.x = acc[mt][nt][half * 2 + 0];
                v.y = acc[mt][nt][half * 2 + 1];
                if (MODE == 1) {
                    float2 xv = *(const float2*)(xrow + col);
                    v.x += xv.x; v.y += xv.y;
                }
                if (MODE == 2) {
                    float2 xv = *(const float2*)(xrow + col);
                    v.x *= xv.x / (1.f + expf(-xv.x));
                    v.y *= xv.y / (1.f + expf(-xv.y));
                }
                if (MODE == 2) {
                    __half2 hv = __floats2half2_rn(v.x, v.y);
                    *(uint32_t*)((__half*)Cout + (size_t)row * N + col) =
                        *(uint32_t*)&hv;
                } else {
                    *(float2*)((float*)Cout + (size_t)row * N + col) = v;
                }
            }
        }
    }
}

// ---------------- RoPE + split qkv -> q,k in [B,H,T,dh] (tf32, q pre-scaled)
#define Q_SCALE (0.125f * 1.44269504088896f)   // 1/sqrt(64) * log2(e)
__global__ void rope_split_kernel(const float* __restrict__ qkv,
                                  float* __restrict__ q,
                                  float* __restrict__ k) {
    int idx = blockIdx.x * blockDim.x + threadIdx.x;
    int i = idx & 31;
    int h = (idx >> 5) & 15;
    int m = idx >> 9;
    int b = m >> 11;
    int t = m & 2047;

    const float* base = qkv + (size_t)m * (3 * C_DIM) + h * DH + 2 * i;
    float q1 = base[0],     q2 = base[1];
    float k1 = base[C_DIM], k2 = base[C_DIM + 1];

    float freq = expf(-(2.0f * (float)i) * (1.0f / 64.0f) * 9.210340371976184f);
    float th = (float)t * freq;
    float s, c;
    sincosf(th, &s, &c);

    size_t o = ((size_t)(b * H_NUM + h) * T_LEN + t) * DH + 2 * i;
    q[o]   = tf32f((q1 * c - q2 * s) * Q_SCALE);
    q[o+1] = tf32f((q1 * s + q2 * c) * Q_SCALE);
    k[o]   = tf32f(k1 * c - k2 * s);
    k[o+1] = tf32f(k1 * s + k2 * c);
}

// ---------------- V transpose: qkv v-section -> [B,H,dh,T], tf32 ------------
__global__ void vtrans_kernel(const float* __restrict__ qkv,
                              float* __restrict__ vt) {
    __shared__ float s[64][65];
    int bh = blockIdx.y;
    int b  = bh >> 4;
    int h  = bh & 15;
    int t0 = blockIdx.x * 64;
    int tid = threadIdx.x;

    for (int idx = tid; idx < 64 * 64; idx += 256) {
        int tok = idx >> 6, d = idx & 63;
        s[tok][d] = qkv[(size_t)(b * T_LEN + t0 + tok) * (3 * C_DIM)
                        + 2 * C_DIM + h * DH + d];
    }
    __syncthreads();
    for (int idx = tid; idx < 64 * 64; idx += 256) {
        int d = idx >> 6, tok = idx & 63;
        vt[((size_t)bh * DH + d) * T_LEN + t0 + tok] = tf32f(s[tok][d]);
    }
}

// ---------------- tensor-core causal flash attention (fp16 output) ----------
#define APAD 68
__global__ __launch_bounds__(128)
void attn_mma_kernel(const float* __restrict__ Q,
                     const float* __restrict__ Kg,
                     const float* __restrict__ Vt,
                     __half* __restrict__ O) {
    extern __shared__ float smf[];
    float* sQ = smf;
    float* sK = smf + 64 * APAD;
    float* sV = smf + 2 * 64 * APAD;

    int bh   = blockIdx.y;
    int b    = bh >> 4;
    int head = bh & 15;
    int q0   = blockIdx.x * 64;
    int tid  = threadIdx.x;
    int warp = tid >> 5;
    int lane = tid & 31;
    int wm   = warp * 16;
    int g    = lane >> 2;
    int t    = lane & 3;
    int i    = lane & 7;
    int sub  = lane >> 3;

    uint32_t smBase = (uint32_t)__cvta_generic_to_shared(smf);
    const uint32_t K_OFF = 64 * APAD * 4;
    const uint32_t V_OFF = 2 * 64 * APAD * 4;

    const float* qg = Q + ((size_t)bh * T_LEN + q0) * DH;
    for (int idx = tid; idx < 64 * 16; idx += 128) {
        int r = idx >> 4, c4 = (idx & 15) * 4;
        *(float4*)&sQ[r * APAD + c4] = *(const float4*)(qg + r * DH + c4);
    }
    __syncthreads();

    uint32_t qf[8][4];
    {
        int row = wm + (sub & 1) * 8 + i;
        #pragma unroll
        for (int kq = 0; kq < 8; kq++) {
            uint32_t off = (uint32_t)(row * APAD + kq * 8 + (sub >> 1) * 4) * 4u;
            ldsm4(qf[kq][0], qf[kq][1], qf[kq][2], qf[kq][3], smBase + off);
        }
    }

    float accO[8][4];
    #pragma unroll
    for (int nt = 0; nt < 8; nt++)
        #pragma unroll
        for (int e = 0; e < 4; e++) accO[nt][e] = 0.f;
    float m0 = -1e30f, m1 = -1e30f, l0 = 0.f, l1 = 0.f;

    int r0 = q0 + wm + g;
    int r1 = r0 + 8;
    int prow0 = (wm + g) * APAD;
    int prow1 = (wm + g + 8) * APAD;
    int arow  = wm + (sub & 1) * 8 + i;

    int ntiles = q0 / 64 + 1;
    for (int kt = 0; kt < ntiles; kt++) {
        int ks = kt * 64;
        const float* kbase = Kg + ((size_t)bh * T_LEN + ks) * DH;
        const float* vbase = Vt + (size_t)bh * DH * T_LEN + ks;
        for (int idx = tid; idx < 64 * 16; idx += 128) {
            int r = idx >> 4, c4 = (idx & 15) * 4;
            *(float4*)&sK[r * APAD + c4] = *(const float4*)(kbase + r * DH + c4);
            *(float4*)&sV[r * APAD + c4] = *(const float4*)(vbase + (size_t)r * T_LEN + c4);
        }
        __syncthreads();

        if (ks <= q0 + wm + 15) {
            float s[8][4];
            #pragma unroll
            for (int nt = 0; nt < 8; nt++)
                #pragma unroll
                for (int e = 0; e < 4; e++) s[nt][e] = 0.f;

            #pragma unroll
            for (int kq = 0; kq < 8; kq++) {
                uint32_t bR[4][4];
                #pragma unroll
                for (int p = 0; p < 4; p++) {
                    int row = p * 16 + (sub >> 1) * 8 + i;
                    uint32_t off = K_OFF +
                        (uint32_t)(row * APAD + kq * 8 + (sub & 1) * 4) * 4u;
                    ldsm4(bR[p][0], bR[p][1], bR[p][2], bR[p][3], smBase + off);
                }
                #pragma unroll
                for (int nt = 0; nt < 8; nt++)
                    mma_tf32(s[nt], qf[kq][0], qf[kq][1], qf[kq][2], qf[kq][3],
                             bR[nt >> 1][(nt & 1) * 2], bR[nt >> 1][(nt & 1) * 2 + 1]);
            }

            if (ks + 63 > q0 + wm) {
                #pragma unroll
                for (int nt = 0; nt < 8; nt++) {
                    int kc = ks + nt * 8 + 2 * t;
                    if (kc     > r0) s[nt][0] = -1e30f;
                    if (kc + 1 > r0) s[nt][1] = -1e30f;
                    if (kc     > r1) s[nt][2] = -1e30f;
                    if (kc + 1 > r1) s[nt][3] = -1e30f;
                }
            }

            float tm0 = -1e30f, tm1 = -1e30f;
            #pragma unroll
            for (int nt = 0; nt < 8; nt++) {
                tm0 = fmaxf(tm0, fmaxf(s[nt][0], s[nt][1]));
                tm1 = fmaxf(tm1, fmaxf(s[nt][2], s[nt][3]));
            }
            tm0 = fmaxf(tm0, __shfl_xor_sync(0xffffffffu, tm0, 1));
            tm0 = fmaxf(tm0, __shfl_xor_sync(0xffffffffu, tm0, 2));
            tm1 = fmaxf(tm1, __shfl_xor_sync(0xffffffffu, tm1, 1));
            tm1 = fmaxf(tm1, __shfl_xor_sync(0xffffffffu, tm1, 2));

            float mn0 = fmaxf(m0, tm0), mn1 = fmaxf(m1, tm1);
            float c0 = exp2f(m0 - mn0), c1 = exp2f(m1 - mn1);

            float ps0 = 0.f, ps1 = 0.f;
            #pragma unroll
            for (int nt = 0; nt < 8; nt++) {
                float2 pa, pb;
                pa.x = exp2f(s[nt][0] - mn0); pa.y = exp2f(s[nt][1] - mn0);
                pb.x = exp2f(s[nt][2] - mn1); pb.y = exp2f(s[nt][3] - mn1);
                ps0 += pa.x + pa.y; ps1 += pb.x + pb.y;
                pa.x = tf32f(pa.x); pa.y = tf32f(pa.y);
                pb.x = tf32f(pb.x); pb.y = tf32f(pb.y);
                int col = nt * 8 + 2 * t;
                *(float2*)&sQ[prow0 + col] = pa;
                *(float2*)&sQ[prow1 + col] = pb;
            }
            ps0 += __shfl_xor_sync(0xffffffffu, ps0, 1);
            ps0 += __shfl_xor_sync(0xffffffffu, ps0, 2);
            ps1 += __shfl_xor_sync(0xffffffffu, ps1, 1);
            ps1 += __shfl_xor_sync(0xffffffffu, ps1, 2);

            l0 = l0 * c0 + ps0;
            l1 = l1 * c1 + ps1;
            m0 = mn0; m1 = mn1;

            #pragma unroll
            for (int nt = 0; nt < 8; nt++) {
                accO[nt][0] *= c0; accO[nt][1] *= c0;
                accO[nt][2] *= c1; accO[nt][3] *= c1;
            }
            __syncwarp();

            #pragma unroll
            for (int kp = 0; kp < 8; kp++) {
                uint32_t aP[4];
                ldsm4(aP[0], aP[1], aP[2], aP[3],
                      smBase + (uint32_t)(arow * APAD + kp * 8 + (sub >> 1) * 4) * 4u);
                uint32_t bV[4][4];
                #pragma unroll
                for (int p = 0; p < 4; p++) {
                    int row = p * 16 + (sub >> 1) * 8 + i;
                    uint32_t off = V_OFF +
                        (uint32_t)(row * APAD + kp * 8 + (sub & 1) * 4) * 4u;
                    ldsm4(bV[p][0], bV[p][1], bV[p][2], bV[p][3], smBase + off);
                }
                #pragma unroll
                for (int nt = 0; nt < 8; nt++)
                    mma_tf32(accO[nt], aP[0], aP[1], aP[2], aP[3],
                             bV[nt >> 1][(nt & 1) * 2], bV[nt >> 1][(nt & 1) * 2 + 1]);
            }
        }
        __syncthreads();
    }

    float inv0 = 1.f / l0, inv1 = 1.f / l1;
    __half* o0 = O + ((size_t)(b * T_LEN + r0)) * C_DIM + head * DH;
    __half* o1 = O + ((size_t)(b * T_LEN + r1)) * C_DIM + head * DH;
    #pragma unroll
    for (int nt = 0; nt < 8; nt++) {
        int col = nt * 8 + 2 * t;
        __half2 h0 = __floats2half2_rn(accO[nt][0] * inv0, accO[nt][1] * inv0);
        __half2 h1 = __floats2half2_rn(accO[nt][2] * inv1, accO[nt][3] * inv1);
        *(uint32_t*)(o0 + col) = *(uint32_t*)&h0;
        *(uint32_t*)(o1 + col) = *(uint32_t*)&h1;
    }
}

// ---------------- launch ----------------------------------------------------
extern "C" void kernel_launch(void* const* d_in, const int* in_sizes, int n_in,
                              void* d_out, int out_size) {
    const float* x      = (const float*)d_in[0];
    const float* w_qkv  = (const float*)d_in[1];
    const float* w_proj = (const float*)d_in[2];
    const float* g1     = (const float*)d_in[3];
    const float* g2     = (const float*)d_in[4];
    const float* w1     = (const float*)d_in[5];
    const float* w2     = (const float*)d_in[6];
    const float* w3     = (const float*)d_in[7];
    float* out = (float*)d_out;

    __half *p_h16, *p_o16, *p_ff16, *p_w16;
    float  *p_qkv, *p_q, *p_k, *p_v, *p_x1, *p_ff;
    cudaGetSymbolAddress((void**)&p_h16,  g_h16);
    cudaGetSymbolAddress((void**)&p_qkv,  g_qkv);
    cudaGetSymbolAddress((void**)&p_q,    g_q);
    cudaGetSymbolAddress((void**)&p_k,    g_k);
    cudaGetSymbolAddress((void**)&p_v,    g_v);
    cudaGetSymbolAddress((void**)&p_o16,  g_o16);
    cudaGetSymbolAddress((void**)&p_x1,   g_x1);
    cudaGetSymbolAddress((void**)&p_ff,   g_ff);
    cudaGetSymbolAddress((void**)&p_ff16, g_ff16);
    cudaGetSymbolAddress((void**)&p_w16,  g_w16);

    __half* w_qkv16  = p_w16;
    __half* w_proj16 = w_qkv16  + 3 * C_DIM * C_DIM;
    __half* w116     = w_proj16 + C_DIM * C_DIM;
    __half* w216     = w116     + 4 * C_DIM * C_DIM;
    __half* w316     = w216     + 4 * C_DIM * C_DIM;

    int attn_smem = 3 * 64 * APAD * 4;
    cudaFuncSetAttribute(attn_mma_kernel,
                         cudaFuncAttributeMaxDynamicSharedMemorySize, attn_smem);

    // weight conversion (one-shot per launch)
    f2h_kernel<<<(3 * C_DIM * C_DIM) / (256 * 8), 256>>>(w_qkv,  w_qkv16);
    f2h_kernel<<<(C_DIM * C_DIM)     / (256 * 8), 256>>>(w_proj, w_proj16);
    f2h_kernel<<<(4 * C_DIM * C_DIM) / (256 * 8), 256>>>(w1,     w116);
    f2h_kernel<<<(4 * C_DIM * C_DIM) / (256 * 8), 256>>>(w2,     w216);
    f2h_kernel<<<(4 * C_DIM * C_DIM) / (256 * 8), 256>>>(w3,     w316);

    rmsnorm_h_kernel<<<M_TOK, 256>>>(x, g1, p_h16);
    hgemm_kernel<0><<<dim3(3 * C_DIM / 128, M_TOK / 128), 256>>>(
        p_h16, w_qkv16, nullptr, p_qkv, M_TOK, 3 * C_DIM, C_DIM);
    rope_split_kernel<<<(M_TOK * H_NUM * 32) / 256, 256>>>(p_qkv, p_q, p_k);
    vtrans_kernel<<<dim3(T_LEN / 64, B_NUM * H_NUM), 256>>>(p_qkv, p_v);
    attn_mma_kernel<<<dim3(T_LEN / 64, B_NUM * H_NUM), 128, attn_smem>>>(
        p_q, p_k, p_v, p_o16);
    hgemm_kernel<1><<<dim3(C_DIM / 128, M_TOK / 128), 256>>>(
        p_o16, w_proj16, x, p_x1, M_TOK, C_DIM, C_DIM);
    rmsnorm_h_kernel<<<M_TOK, 256>>>(p_x1, g2, p_h16);
    hgemm_kernel<0><<<dim3(FF_DIM / 128, M_TOK / 128), 256>>>(
        p_h16, w116, nullptr, p_ff, M_TOK, FF_DIM, C_DIM);
    hgemm_kernel<2><<<dim3(FF_DIM / 128, M_TOK / 128), 256>>>(
        p_h16, w316, p_ff, p_ff16, M_TOK, FF_DIM, C_DIM);
    hgemm_kernel<1><<<dim3(C_DIM / 128, M_TOK / 128), 256>>>(
        p_ff16, w216, p_x1, out, M_TOK, C_DIM, FF_DIM);
}

// round 9
// speedup vs baseline: 1.9533x; 1.0976x over previous
#include <cuda_runtime.h>
#include <cuda_fp16.h>
#include <math.h>
#include <stdint.h>

#define C_DIM   1024
#define H_NUM   16
#define DH      64
#define FF_DIM  4096
#define B_NUM   2
#define T_LEN   2048
#define M_TOK   4096   // B*T

// ---------------- scratch (device globals; no allocation allowed) ----------
__device__ __half g_h16 [M_TOK * C_DIM];       // rmsnorm out (fp16)
__device__ float  g_qkv [M_TOK * 3 * C_DIM];
__device__ __half g_q16 [M_TOK * C_DIM];       // [B,H,T,dh] (pre-scaled fp16)
__device__ __half g_k16 [M_TOK * C_DIM];       // [B,H,T,dh] fp16
__device__ __half g_v16 [M_TOK * C_DIM];       // [B,H,dh,T] fp16 (transposed)
__device__ __half g_o16 [M_TOK * C_DIM];       // attention out (fp16)
__device__ float  g_x1  [M_TOK * C_DIM];
__device__ float  g_ff  [M_TOK * FF_DIM];      // a = h2 @ w1^T (fp32)
__device__ __half g_ff16[M_TOK * FF_DIM];      // silu(a)*b (fp16)
__device__ __half g_w16 [(3 + 1 + 4 + 4 + 4) * C_DIM * C_DIM];  // weights fp16

// ---------------- helpers ----------------------------------------------------
__device__ __forceinline__ void mma_f16(float c[4],
                                        uint32_t a0, uint32_t a1, uint32_t a2, uint32_t a3,
                                        uint32_t b0, uint32_t b1) {
    asm volatile(
        "mma.sync.aligned.m16n8k16.row.col.f32.f16.f16.f32 "
        "{%0,%1,%2,%3}, {%4,%5,%6,%7}, {%8,%9}, {%0,%1,%2,%3};\n"
        : "+f"(c[0]), "+f"(c[1]), "+f"(c[2]), "+f"(c[3])
        : "r"(a0), "r"(a1), "r"(a2), "r"(a3), "r"(b0), "r"(b1));
}
__device__ __forceinline__ void ldsm4(uint32_t& r0, uint32_t& r1,
                                      uint32_t& r2, uint32_t& r3, uint32_t addr) {
    asm volatile("ldmatrix.sync.aligned.m8n8.x4.shared.b16 {%0,%1,%2,%3}, [%4];"
                 : "=r"(r0), "=r"(r1), "=r"(r2), "=r"(r3) : "r"(addr));
}

// ---------------- fp32 -> fp16 convert (8 elems/thread) ---------------------
__global__ void f2h_kernel(const float* __restrict__ in, __half* __restrict__ out) {
    int idx = (blockIdx.x * blockDim.x + threadIdx.x) * 8;
    float4 a = *(const float4*)(in + idx);
    float4 b = *(const float4*)(in + idx + 4);
    __half2 h0 = __floats2half2_rn(a.x, a.y);
    __half2 h1 = __floats2half2_rn(a.z, a.w);
    __half2 h2 = __floats2half2_rn(b.x, b.y);
    __half2 h3 = __floats2half2_rn(b.z, b.w);
    uint4 u;
    u.x = *(uint32_t*)&h0; u.y = *(uint32_t*)&h1;
    u.z = *(uint32_t*)&h2; u.w = *(uint32_t*)&h3;
    *(uint4*)(out + idx) = u;
}

// ---------------- RMSNorm -> fp16 --------------------------------------------
__global__ void rmsnorm_h_kernel(const float* __restrict__ x,
                                 const float* __restrict__ g,
                                 __half* __restrict__ y) {
    int row = blockIdx.x;
    int tid = threadIdx.x;
    const float4* xr = (const float4*)(x + (size_t)row * C_DIM);
    const float4* gr = (const float4*)g;

    float4 xv = xr[tid];
    float ss = xv.x*xv.x + xv.y*xv.y + xv.z*xv.z + xv.w*xv.w;
    #pragma unroll
    for (int off = 16; off > 0; off >>= 1)
        ss += __shfl_xor_sync(0xffffffffu, ss, off);
    __shared__ float red[8];
    if ((tid & 31) == 0) red[tid >> 5] = ss;
    __syncthreads();
    float tot = 0.f;
    #pragma unroll
    for (int i = 0; i < 8; i++) tot += red[i];
    float inv = rsqrtf(tot * (1.0f / C_DIM) + 1e-5f);

    float4 gv = gr[tid];
    __half2 h0 = __floats2half2_rn(xv.x * gv.x * inv, xv.y * gv.y * inv);
    __half2 h1 = __floats2half2_rn(xv.z * gv.z * inv, xv.w * gv.w * inv);
    uint2 u;
    u.x = *(uint32_t*)&h0; u.y = *(uint32_t*)&h1;
    *(uint2*)(y + (size_t)row * C_DIM + tid * 4) = u;
}

// ---------------- fp16 tensor-core GEMM (unchanged from R8) -----------------
template <int MODE>
__global__ __launch_bounds__(256, 2)
void hgemm_kernel(const __half* __restrict__ A, const __half* __restrict__ W,
                  const float* X, void* Cout, int M, int N, int K) {
    __shared__ __align__(16) __half sA[2][128 * 16];
    __shared__ __align__(16) __half sB[2][128 * 16];

    int tid  = threadIdx.x;
    int bm   = blockIdx.y * 128;
    int bn   = blockIdx.x * 128;
    int warp = tid >> 5;
    int lane = tid & 31;
    int wm   = (warp >> 1) * 32;
    int wn   = (warp & 1) * 64;

    int lr = tid >> 1;
    int hf = tid & 1;
    const __half* Aptr = A + (size_t)(bm + lr) * K + hf * 8;
    const __half* Wptr = W + (size_t)(bn + lr) * K + hf * 8;
    int sidx = lr * 16 + (hf ^ ((lr >> 2) & 1)) * 8;

    uint32_t aBase = (uint32_t)__cvta_generic_to_shared(&sA[0][0]);
    uint32_t bBase = (uint32_t)__cvta_generic_to_shared(&sB[0][0]);

    int l15 = lane & 15, lh = lane >> 4;
    uint32_t offA[2];
    #pragma unroll
    for (int mt = 0; mt < 2; mt++) {
        int row = wm + mt * 16 + l15;
        int u   = lh ^ ((row >> 2) & 1);
        offA[mt] = (uint32_t)(row * 16 + u * 8) * 2u;
    }
    uint32_t offB[2][2];
    #pragma unroll
    for (int kh = 0; kh < 2; kh++)
        #pragma unroll
        for (int gb = 0; gb < 2; gb++) {
            int row = wn + gb * 32 + lane;
            int u   = kh ^ ((row >> 2) & 1);
            offB[kh][gb] = (uint32_t)(row * 16 + u * 8) * 2u;
        }

    float acc[2][8][4];
    #pragma unroll
    for (int mt = 0; mt < 2; mt++)
        #pragma unroll
        for (int nt = 0; nt < 8; nt++)
            #pragma unroll
            for (int e = 0; e < 4; e++) acc[mt][nt][e] = 0.f;

    *(uint4*)&sA[0][sidx] = *(const uint4*)(Aptr);
    *(uint4*)&sB[0][sidx] = *(const uint4*)(Wptr);
    __syncthreads();

    int NC = K >> 4;
    int st = 0;
    for (int ck = 0; ck < NC; ck++) {
        bool more = (ck + 1) < NC;
        uint4 na, nb;
        if (more) {
            na = *(const uint4*)(Aptr + (ck + 1) * 16);
            nb = *(const uint4*)(Wptr + (ck + 1) * 16);
        }

        uint32_t tA = aBase + st * (128 * 16 * 2);
        uint32_t tB = bBase + st * (128 * 16 * 2);
        uint32_t aR[2][4], bR[2][2][4];
        ldsm4(aR[0][0], aR[0][1], aR[0][2], aR[0][3], tA + offA[0]);
        ldsm4(aR[1][0], aR[1][1], aR[1][2], aR[1][3], tA + offA[1]);
        #pragma unroll
        for (int kh = 0; kh < 2; kh++)
            #pragma unroll
            for (int gb = 0; gb < 2; gb++)
                ldsm4(bR[kh][gb][0], bR[kh][gb][1], bR[kh][gb][2], bR[kh][gb][3],
                      tB + offB[kh][gb]);

        #pragma unroll
        for (int mt = 0; mt < 2; mt++)
            #pragma unroll
            for (int nt = 0; nt < 8; nt++)
                mma_f16(acc[mt][nt],
                        aR[mt][0], aR[mt][1], aR[mt][2], aR[mt][3],
                        bR[0][nt >> 2][nt & 3], bR[1][nt >> 2][nt & 3]);

        if (more) {
            *(uint4*)&sA[st ^ 1][sidx] = na;
            *(uint4*)&sB[st ^ 1][sidx] = nb;
        }
        __syncthreads();
        st ^= 1;
    }

    int g = lane >> 2;
    int t = lane & 3;
    #pragma unroll
    for (int mt = 0; mt < 2; mt++) {
        #pragma unroll
        for (int half = 0; half < 2; half++) {
            int row = bm + wm + mt * 16 + half * 8 + g;
            const float* xrow = (MODE != 0) ? (X + (size_t)row * N) : nullptr;
            #pragma unroll
            for (int nt = 0; nt < 8; nt++) {
                int col = bn + wn + nt * 8 + 2 * t;
                float2 v;
                v.x = acc[mt][nt][half * 2 + 0];
                v.y = acc[mt][nt][half * 2 + 1];
                if (MODE == 1) {
                    float2 xv = *(const float2*)(xrow + col);
                    v.x += xv.x; v.y += xv.y;
                }
                if (MODE == 2) {
                    float2 xv = *(const float2*)(xrow + col);
                    v.x *= xv.x / (1.f + expf(-xv.x));
                    v.y *= xv.y / (1.f + expf(-xv.y));
                }
                if (MODE == 2) {
                    __half2 hv = __floats2half2_rn(v.x, v.y);
                    *(uint32_t*)((__half*)Cout + (size_t)row * N + col) =
                        *(uint32_t*)&hv;
                } else {
                    *(float2*)((float*)Cout + (size_t)row * N + col) = v;
                }
            }
        }
    }
}

// ---------------- RoPE + split qkv -> q,k fp16 [B,H,T,dh] -------------------
#define Q_SCALE (0.125f * 1.44269504088896f)   // 1/sqrt(64) * log2(e)
__global__ void rope_split_h_kernel(const float* __restrict__ qkv,
                                    __half* __restrict__ q,
                                    __half* __restrict__ k) {
    int idx = blockIdx.x * blockDim.x + threadIdx.x;
    int i = idx & 31;
    int h = (idx >> 5) & 15;
    int m = idx >> 9;
    int b = m >> 11;
    int t = m & 2047;

    const float* base = qkv + (size_t)m * (3 * C_DIM) + h * DH + 2 * i;
    float q1 = base[0],     q2 = base[1];
    float k1 = base[C_DIM], k2 = base[C_DIM + 1];

    float freq = expf(-(2.0f * (float)i) * (1.0f / 64.0f) * 9.210340371976184f);
    float th = (float)t * freq;
    float s, c;
    sincosf(th, &s, &c);

    size_t o = ((size_t)(b * H_NUM + h) * T_LEN + t) * DH + 2 * i;
    __half2 qh = __floats2half2_rn((q1 * c - q2 * s) * Q_SCALE,
                                   (q1 * s + q2 * c) * Q_SCALE);
    __half2 kh = __floats2half2_rn(k1 * c - k2 * s, k1 * s + k2 * c);
    *(uint32_t*)(q + o) = *(uint32_t*)&qh;
    *(uint32_t*)(k + o) = *(uint32_t*)&kh;
}

// ---------------- V transpose: qkv v-section -> [B,H,dh,T] fp16 -------------
__global__ void vtrans_h_kernel(const float* __restrict__ qkv,
                                __half* __restrict__ vt) {
    __shared__ float s[64][65];
    int bh = blockIdx.y;
    int b  = bh >> 4;
    int h  = bh & 15;
    int t0 = blockIdx.x * 64;
    int tid = threadIdx.x;

    for (int idx = tid; idx < 64 * 64; idx += 256) {
        int tok = idx >> 6, d = idx & 63;
        s[tok][d] = qkv[(size_t)(b * T_LEN + t0 + tok) * (3 * C_DIM)
                        + 2 * C_DIM + h * DH + d];
    }
    __syncthreads();
    for (int idx = tid; idx < 64 * 32; idx += 256) {
        int d = idx >> 5, tp = idx & 31;
        __half2 hv = __floats2half2_rn(s[2 * tp][d], s[2 * tp + 1][d]);
        *(uint32_t*)(vt + ((size_t)bh * DH + d) * T_LEN + t0 + 2 * tp) =
            *(uint32_t*)&hv;
    }
}

// ---------------- fp16 tensor-core causal flash attention -------------------
// grid (T/64, B*H), 128 threads (4 warps x 16 query rows). All f16 mma.
// smem tiles: 64 rows x 72 halves (144B rows -> 4-bank shift, conflict-free).
#define HPAD 72
__global__ __launch_bounds__(128)
void attn_h_kernel(const __half* __restrict__ Q,
                   const __half* __restrict__ Kg,
                   const __half* __restrict__ Vt,
                   __half* __restrict__ O) {
    __shared__ __align__(16) __half sQ[64 * HPAD];   // later: P
    __shared__ __align__(16) __half sK[64 * HPAD];
    __shared__ __align__(16) __half sV[64 * HPAD];

    int bh   = blockIdx.y;
    int b    = bh >> 4;
    int head = bh & 15;
    int q0   = blockIdx.x * 64;
    int tid  = threadIdx.x;
    int warp = tid >> 5;
    int lane = tid & 31;
    int wm   = warp * 16;
    int g    = lane >> 2;
    int t    = lane & 3;
    int l15  = lane & 15;
    int lh   = lane >> 4;

    uint32_t qB = (uint32_t)__cvta_generic_to_shared(sQ);
    uint32_t kB = (uint32_t)__cvta_generic_to_shared(sK);
    uint32_t vB = (uint32_t)__cvta_generic_to_shared(sV);

    // load Q tile (64 x 64 halves = 512 16B units)
    const __half* qg = Q + ((size_t)bh * T_LEN + q0) * DH;
    #pragma unroll
    for (int idx = tid; idx < 512; idx += 128) {
        int r = idx >> 3, u = idx & 7;
        *(uint4*)&sQ[r * HPAD + u * 8] = *(const uint4*)(qg + r * DH + u * 8);
    }
    __syncthreads();

    // Q fragments: 4 k16 chunks, held in registers
    uint32_t qf[4][4];
    #pragma unroll
    for (int kc = 0; kc < 4; kc++) {
        int row = wm + l15;
        int u   = kc * 2 + lh;
        ldsm4(qf[kc][0], qf[kc][1], qf[kc][2], qf[kc][3],
              qB + (uint32_t)(row * HPAD + u * 8) * 2u);
    }
    __syncthreads();   // sQ now reusable as P

    float accO[8][4];
    #pragma unroll
    for (int nt = 0; nt < 8; nt++)
        #pragma unroll
        for (int e = 0; e < 4; e++) accO[nt][e] = 0.f;
    float m0 = -1e30f, m1 = -1e30f, l0 = 0.f, l1 = 0.f;

    int r0 = q0 + wm + g;
    int r1 = r0 + 8;
    int prow0 = (wm + g) * HPAD;
    int prow1 = (wm + g + 8) * HPAD;

    int ntiles = q0 / 64 + 1;
    for (int kt = 0; kt < ntiles; kt++) {
        int ks = kt * 64;
        const __half* kbase = Kg + ((size_t)bh * T_LEN + ks) * DH;
        const __half* vbase = Vt + (size_t)bh * DH * T_LEN + ks;
        #pragma unroll
        for (int idx = tid; idx < 512; idx += 128) {
            int r = idx >> 3, u = idx & 7;
            *(uint4*)&sK[r * HPAD + u * 8] = *(const uint4*)(kbase + r * DH + u * 8);
            *(uint4*)&sV[r * HPAD + u * 8] =
                *(const uint4*)(vbase + (size_t)r * T_LEN + u * 8);
        }
        __syncthreads();

        if (ks <= q0 + wm + 15) {
            // ---- S = Q @ K^T (f16 mma, fp32 accum) ----
            float s[8][4];
            #pragma unroll
            for (int nt = 0; nt < 8; nt++)
                #pragma unroll
                for (int e = 0; e < 4; e++) s[nt][e] = 0.f;

            #pragma unroll
            for (int kc = 0; kc < 4; kc++) {
                uint32_t bR[2][2][4];
                #pragma unroll
                for (int kh = 0; kh < 2; kh++)
                    #pragma unroll
                    for (int gb = 0; gb < 2; gb++) {
                        int row = gb * 32 + lane;
                        int u   = kc * 2 + kh;
                        ldsm4(bR[kh][gb][0], bR[kh][gb][1],
                              bR[kh][gb][2], bR[kh][gb][3],
                              kB + (uint32_t)(row * HPAD + u * 8) * 2u);
                    }
                #pragma unroll
                for (int nt = 0; nt < 8; nt++)
                    mma_f16(s[nt], qf[kc][0], qf[kc][1], qf[kc][2], qf[kc][3],
                            bR[0][nt >> 2][nt & 3], bR[1][nt >> 2][nt & 3]);
            }

            // ---- causal mask ----
            if (ks + 63 > q0 + wm) {
                #pragma unroll
                for (int nt = 0; nt < 8; nt++) {
                    int kc = ks + nt * 8 + 2 * t;
                    if (kc     > r0) s[nt][0] = -1e30f;
                    if (kc + 1 > r0) s[nt][1] = -1e30f;
                    if (kc     > r1) s[nt][2] = -1e30f;
                    if (kc + 1 > r1) s[nt][3] = -1e30f;
                }
            }

            // ---- online softmax (log2 domain; Q pre-scaled) ----
            float tm0 = -1e30f, tm1 = -1e30f;
            #pragma unroll
            for (int nt = 0; nt < 8; nt++) {
                tm0 = fmaxf(tm0, fmaxf(s[nt][0], s[nt][1]));
                tm1 = fmaxf(tm1, fmaxf(s[nt][2], s[nt][3]));
            }
            tm0 = fmaxf(tm0, __shfl_xor_sync(0xffffffffu, tm0, 1));
            tm0 = fmaxf(tm0, __shfl_xor_sync(0xffffffffu, tm0, 2));
            tm1 = fmaxf(tm1, __shfl_xor_sync(0xffffffffu, tm1, 1));
            tm1 = fmaxf(tm1, __shfl_xor_sync(0xffffffffu, tm1, 2));

            float mn0 = fmaxf(m0, tm0), mn1 = fmaxf(m1, tm1);
            float c0 = exp2f(m0 - mn0), c1 = exp2f(m1 - mn1);

            float ps0 = 0.f, ps1 = 0.f;
            #pragma unroll
            for (int nt = 0; nt < 8; nt++) {
                float pa0 = exp2f(s[nt][0] - mn0), pa1 = exp2f(s[nt][1] - mn0);
                float pb0 = exp2f(s[nt][2] - mn1), pb1 = exp2f(s[nt][3] - mn1);
                ps0 += pa0 + pa1; ps1 += pb0 + pb1;
                __half2 ha = __floats2half2_rn(pa0, pa1);
                __half2 hb = __floats2half2_rn(pb0, pb1);
                int col = nt * 8 + 2 * t;
                *(uint32_t*)&sQ[prow0 + col] = *(uint32_t*)&ha;
                *(uint32_t*)&sQ[prow1 + col] = *(uint32_t*)&hb;
            }
            ps0 += __shfl_xor_sync(0xffffffffu, ps0, 1);
            ps0 += __shfl_xor_sync(0xffffffffu, ps0, 2);
            ps1 += __shfl_xor_sync(0xffffffffu, ps1, 1);
            ps1 += __shfl_xor_sync(0xffffffffu, ps1, 2);

            l0 = l0 * c0 + ps0;
            l1 = l1 * c1 + ps1;
            m0 = mn0; m1 = mn1;

            #pragma unroll
            for (int nt = 0; nt < 8; nt++) {
                accO[nt][0] *= c0; accO[nt][1] *= c0;
                accO[nt][2] *= c1; accO[nt][3] *= c1;
            }
            __syncwarp();

            // ---- O += P @ V  (A = own-warp P rows, B = V^T tile) ----
            #pragma unroll
            for (int kc = 0; kc < 4; kc++) {
                uint32_t aP[4];
                {
                    int row = wm + l15;
                    int u   = kc * 2 + lh;
                    ldsm4(aP[0], aP[1], aP[2], aP[3],
                          qB + (uint32_t)(row * HPAD + u * 8) * 2u);
                }
                uint32_t bV[2][2][4];
                #pragma unroll
                for (int kh = 0; kh < 2; kh++)
                    #pragma unroll
                    for (int gb = 0; gb < 2; gb++) {
                        int row = gb * 32 + lane;
                        int u   = kc * 2 + kh;
                        ldsm4(bV[kh][gb][0], bV[kh][gb][1],
                              bV[kh][gb][2], bV[kh][gb][3],
                              vB + (uint32_t)(row * HPAD + u * 8) * 2u);
                    }
                #pragma unroll
                for (int nt = 0; nt < 8; nt++)
                    mma_f16(accO[nt], aP[0], aP[1], aP[2], aP[3],
                            bV[0][nt >> 2][nt & 3], bV[1][nt >> 2][nt & 3]);
            }
        }
        __syncthreads();
    }

    // ---- epilogue (fp16 out) ----
    float inv0 = 1.f / l0, inv1 = 1.f / l1;
    __half* o0 = O + ((size_t)(b * T_LEN + r0)) * C_DIM + head * DH;
    __half* o1 = O + ((size_t)(b * T_LEN + r1)) * C_DIM + head * DH;
    #pragma unroll
    for (int nt = 0; nt < 8; nt++) {
        int col = nt * 8 + 2 * t;
        __half2 h0 = __floats2half2_rn(accO[nt][0] * inv0, accO[nt][1] * inv0);
        __half2 h1 = __floats2half2_rn(accO[nt][2] * inv1, accO[nt][3] * inv1);
        *(uint32_t*)(o0 + col) = *(uint32_t*)&h0;
        *(uint32_t*)(o1 + col) = *(uint32_t*)&h1;
    }
}

// ---------------- launch ----------------------------------------------------
extern "C" void kernel_launch(void* const* d_in, const int* in_sizes, int n_in,
                              void* d_out, int out_size) {
    const float* x      = (const float*)d_in[0];
    const float* w_qkv  = (const float*)d_in[1];
    const float* w_proj = (const float*)d_in[2];
    const float* g1     = (const float*)d_in[3];
    const float* g2     = (const float*)d_in[4];
    const float* w1     = (const float*)d_in[5];
    const float* w2     = (const float*)d_in[6];
    const float* w3     = (const float*)d_in[7];
    float* out = (float*)d_out;

    __half *p_h16, *p_q16, *p_k16, *p_v16, *p_o16, *p_ff16, *p_w16;
    float  *p_qkv, *p_x1, *p_ff;
    cudaGetSymbolAddress((void**)&p_h16,  g_h16);
    cudaGetSymbolAddress((void**)&p_qkv,  g_qkv);
    cudaGetSymbolAddress((void**)&p_q16,  g_q16);
    cudaGetSymbolAddress((void**)&p_k16,  g_k16);
    cudaGetSymbolAddress((void**)&p_v16,  g_v16);
    cudaGetSymbolAddress((void**)&p_o16,  g_o16);
    cudaGetSymbolAddress((void**)&p_x1,   g_x1);
    cudaGetSymbolAddress((void**)&p_ff,   g_ff);
    cudaGetSymbolAddress((void**)&p_ff16, g_ff16);
    cudaGetSymbolAddress((void**)&p_w16,  g_w16);

    __half* w_qkv16  = p_w16;
    __half* w_proj16 = w_qkv16  + 3 * C_DIM * C_DIM;
    __half* w116     = w_proj16 + C_DIM * C_DIM;
    __half* w216     = w116     + 4 * C_DIM * C_DIM;
    __half* w316     = w216     + 4 * C_DIM * C_DIM;

    // weight conversion (one-shot per launch)
    f2h_kernel<<<(3 * C_DIM * C_DIM) / (256 * 8), 256>>>(w_qkv,  w_qkv16);
    f2h_kernel<<<(C_DIM * C_DIM)     / (256 * 8), 256>>>(w_proj, w_proj16);
    f2h_kernel<<<(4 * C_DIM * C_DIM) / (256 * 8), 256>>>(w1,     w116);
    f2h_kernel<<<(4 * C_DIM * C_DIM) / (256 * 8), 256>>>(w2,     w216);
    f2h_kernel<<<(4 * C_DIM * C_DIM) / (256 * 8), 256>>>(w3,     w316);

    rmsnorm_h_kernel<<<M_TOK, 256>>>(x, g1, p_h16);
    hgemm_kernel<0><<<dim3(3 * C_DIM / 128, M_TOK / 128), 256>>>(
        p_h16, w_qkv16, nullptr, p_qkv, M_TOK, 3 * C_DIM, C_DIM);
    rope_split_h_kernel<<<(M_TOK * H_NUM * 32) / 256, 256>>>(p_qkv, p_q16, p_k16);
    vtrans_h_kernel<<<dim3(T_LEN / 64, B_NUM * H_NUM), 256>>>(p_qkv, p_v16);
    attn_h_kernel<<<dim3(T_LEN / 64, B_NUM * H_NUM), 128>>>(
        p_q16, p_k16, p_v16, p_o16);
    hgemm_kernel<1><<<dim3(C_DIM / 128, M_TOK / 128), 256>>>(
        p_o16, w_proj16, x, p_x1, M_TOK, C_DIM, C_DIM);
    rmsnorm_h_kernel<<<M_TOK, 256>>>(p_x1, g2, p_h16);
    hgemm_kernel<0><<<dim3(FF_DIM / 128, M_TOK / 128), 256>>>(
        p_h16, w116, nullptr, p_ff, M_TOK, FF_DIM, C_DIM);
    hgemm_kernel<2><<<dim3(FF_DIM / 128, M_TOK / 128), 256>>>(
        p_h16, w316, p_ff, p_ff16, M_TOK, FF_DIM, C_DIM);
    hgemm_kernel<1><<<dim3(C_DIM / 128, M_TOK / 128), 256>>>(
        p_ff16, w216, p_x1, out, M_TOK, C_DIM, FF_DIM);
}

// round 10
// speedup vs baseline: 2.3547x; 1.2055x over previous
#include <cuda_runtime.h>
#include <cuda_fp16.h>
#include <math.h>
#include <stdint.h>

#define C_DIM   1024
#define H_NUM   16
#define DH      64
#define FF_DIM  4096
#define B_NUM   2
#define T_LEN   2048
#define M_TOK   4096   // B*T

// ---------------- scratch (device globals; no allocation allowed) ----------
__device__ __half g_h16 [M_TOK * C_DIM];       // rmsnorm out (fp16)
__device__ float  g_qkv [M_TOK * 3 * C_DIM];
__device__ __half g_q16 [M_TOK * C_DIM];       // [B,H,T,dh] (pre-scaled fp16)
__device__ __half g_k16 [M_TOK * C_DIM];       // [B,H,T,dh] fp16
__device__ __half g_v16 [M_TOK * C_DIM];       // [B,H,dh,T] fp16 (transposed)
__device__ __half g_o16 [M_TOK * C_DIM];       // attention out (fp16)
__device__ float  g_x1  [M_TOK * C_DIM];
__device__ float  g_ff  [M_TOK * FF_DIM];      // a = h2 @ w1^T (fp32)
__device__ __half g_ff16[M_TOK * FF_DIM];      // silu(a)*b (fp16)
__device__ __half g_w16 [(3 + 1 + 4 + 4 + 4) * C_DIM * C_DIM];  // weights fp16

// ---------------- helpers ----------------------------------------------------
__device__ __forceinline__ void mma_f16(float c[4],
                                        uint32_t a0, uint32_t a1, uint32_t a2, uint32_t a3,
                                        uint32_t b0, uint32_t b1) {
    asm volatile(
        "mma.sync.aligned.m16n8k16.row.col.f32.f16.f16.f32 "
        "{%0,%1,%2,%3}, {%4,%5,%6,%7}, {%8,%9}, {%0,%1,%2,%3};\n"
        : "+f"(c[0]), "+f"(c[1]), "+f"(c[2]), "+f"(c[3])
        : "r"(a0), "r"(a1), "r"(a2), "r"(a3), "r"(b0), "r"(b1));
}
__device__ __forceinline__ void ldsm4(uint32_t& r0, uint32_t& r1,
                                      uint32_t& r2, uint32_t& r3, uint32_t addr) {
    asm volatile("ldmatrix.sync.aligned.m8n8.x4.shared.b16 {%0,%1,%2,%3}, [%4];"
                 : "=r"(r0), "=r"(r1), "=r"(r2), "=r"(r3) : "r"(addr));
}
__device__ __forceinline__ void cp16(uint32_t dst, const void* src) {
    asm volatile("cp.async.cg.shared.global [%0], [%1], 16;" :: "r"(dst), "l"(src));
}

// ---------------- fp32 -> fp16 convert (8 elems/thread) ---------------------
__global__ void f2h_kernel(const float* __restrict__ in, __half* __restrict__ out) {
    int idx = (blockIdx.x * blockDim.x + threadIdx.x) * 8;
    float4 a = *(const float4*)(in + idx);
    float4 b = *(const float4*)(in + idx + 4);
    __half2 h0 = __floats2half2_rn(a.x, a.y);
    __half2 h1 = __floats2half2_rn(a.z, a.w);
    __half2 h2 = __floats2half2_rn(b.x, b.y);
    __half2 h3 = __floats2half2_rn(b.z, b.w);
    uint4 u;
    u.x = *(uint32_t*)&h0; u.y = *(uint32_t*)&h1;
    u.z = *(uint32_t*)&h2; u.w = *(uint32_t*)&h3;
    *(uint4*)(out + idx) = u;
}

// ---------------- RMSNorm -> fp16 --------------------------------------------
__global__ void rmsnorm_h_kernel(const float* __restrict__ x,
                                 const float* __restrict__ g,
                                 __half* __restrict__ y) {
    int row = blockIdx.x;
    int tid = threadIdx.x;
    const float4* xr = (const float4*)(x + (size_t)row * C_DIM);
    const float4* gr = (const float4*)g;

    float4 xv = xr[tid];
    float ss = xv.x*xv.x + xv.y*xv.y + xv.z*xv.z + xv.w*xv.w;
    #pragma unroll
    for (int off = 16; off > 0; off >>= 1)
        ss += __shfl_xor_sync(0xffffffffu, ss, off);
    __shared__ float red[8];
    if ((tid & 31) == 0) red[tid >> 5] = ss;
    __syncthreads();
    float tot = 0.f;
    #pragma unroll
    for (int i = 0; i < 8; i++) tot += red[i];
    float inv = rsqrtf(tot * (1.0f / C_DIM) + 1e-5f);

    float4 gv = gr[tid];
    __half2 h0 = __floats2half2_rn(xv.x * gv.x * inv, xv.y * gv.y * inv);
    __half2 h1 = __floats2half2_rn(xv.z * gv.z * inv, xv.w * gv.w * inv);
    uint2 u;
    u.x = *(uint32_t*)&h0; u.y = *(uint32_t*)&h1;
    *(uint2*)(y + (size_t)row * C_DIM + tid * 4) = u;
}

// ---------------- fp16 tensor-core GEMM: C[M,N] = A[M,K] @ W[N,K]^T ---------
// Block 128x128, BK=16, 4-stage cp.async pipeline (fp16 data -> 2 LDGSTS/thr/k16).
// 8 warps (4m x 2n), warp tile 32x64, fragments via ldmatrix.x4.
// MODE 0: fp32 out  MODE 1: fp32 out + X residual  MODE 2: fp16 out, silu(X)*acc
#define GSTAGE 4
template <int MODE>
__global__ __launch_bounds__(256, 2)
void hgemm_kernel(const __half* __restrict__ A, const __half* __restrict__ W,
                  const float* X, void* Cout, int M, int N, int K) {
    __shared__ __align__(16) __half sA[GSTAGE][128 * 16];
    __shared__ __align__(16) __half sB[GSTAGE][128 * 16];

    int tid  = threadIdx.x;
    int bm   = blockIdx.y * 128;
    int bn   = blockIdx.x * 128;
    int warp = tid >> 5;
    int lane = tid & 31;
    int wm   = (warp >> 1) * 32;
    int wn   = (warp & 1) * 64;

    // global load / smem store mapping: row = tid>>1, k-octet hf = tid&1
    int lr = tid >> 1;
    int hf = tid & 1;
    const __half* Aptr = A + (size_t)(bm + lr) * K + hf * 8;
    const __half* Wptr = W + (size_t)(bn + lr) * K + hf * 8;
    uint32_t sOff = (uint32_t)(lr * 16 + (hf ^ ((lr >> 2) & 1)) * 8) * 2u;  // bytes

    uint32_t aBase = (uint32_t)__cvta_generic_to_shared(&sA[0][0]);
    uint32_t bBase = (uint32_t)__cvta_generic_to_shared(&sB[0][0]);

    // ldmatrix offsets
    int l15 = lane & 15, lh = lane >> 4;
    uint32_t offA[2];
    #pragma unroll
    for (int mt = 0; mt < 2; mt++) {
        int row = wm + mt * 16 + l15;
        int u   = lh ^ ((row >> 2) & 1);
        offA[mt] = (uint32_t)(row * 16 + u * 8) * 2u;
    }
    uint32_t offB[2][2];   // [k-octet][n-group of 32]
    #pragma unroll
    for (int kh = 0; kh < 2; kh++)
        #pragma unroll
        for (int gb = 0; gb < 2; gb++) {
            int row = wn + gb * 32 + lane;
            int u   = kh ^ ((row >> 2) & 1);
            offB[kh][gb] = (uint32_t)(row * 16 + u * 8) * 2u;
        }

    float acc[2][8][4];
    #pragma unroll
    for (int mt = 0; mt < 2; mt++)
        #pragma unroll
        for (int nt = 0; nt < 8; nt++)
            #pragma unroll
            for (int e = 0; e < 4; e++) acc[mt][nt][e] = 0.f;

    int NC = K >> 4;   // k16 chunks

    // prologue: stages 0..2 in flight
    #pragma unroll
    for (int s = 0; s < GSTAGE - 1; s++) {
        cp16(aBase + s * 4096u + sOff, Aptr + s * 16);
        cp16(bBase + s * 4096u + sOff, Wptr + s * 16);
        asm volatile("cp.async.commit_group;" ::: "memory");
    }

    for (int ck = 0; ck < NC; ck++) {
        int st = ck & (GSTAGE - 1);
        asm volatile("cp.async.wait_group %0;" :: "n"(GSTAGE - 2) : "memory");
        __syncthreads();

        uint32_t tA = aBase + st * 4096u;
        uint32_t tB = bBase + st * 4096u;
        uint32_t aR[2][4], bR[2][2][4];
        ldsm4(aR[0][0], aR[0][1], aR[0][2], aR[0][3], tA + offA[0]);
        ldsm4(aR[1][0], aR[1][1], aR[1][2], aR[1][3], tA + offA[1]);
        #pragma unroll
        for (int kh = 0; kh < 2; kh++)
            #pragma unroll
            for (int gb = 0; gb < 2; gb++)
                ldsm4(bR[kh][gb][0], bR[kh][gb][1], bR[kh][gb][2], bR[kh][gb][3],
                      tB + offB[kh][gb]);

        #pragma unroll
        for (int mt = 0; mt < 2; mt++)
            #pragma unroll
            for (int nt = 0; nt < 8; nt++)
                mma_f16(acc[mt][nt],
                        aR[mt][0], aR[mt][1], aR[mt][2], aR[mt][3],
                        bR[0][nt >> 2][nt & 3], bR[1][nt >> 2][nt & 3]);

        int cn = ck + GSTAGE - 1;
        if (cn < NC) {
            uint32_t sn = (uint32_t)(cn & (GSTAGE - 1)) * 4096u;
            cp16(aBase + sn + sOff, Aptr + cn * 16);
            cp16(bBase + sn + sOff, Wptr + cn * 16);
        }
        asm volatile("cp.async.commit_group;" ::: "memory");
    }

    // epilogue
    int g = lane >> 2;
    int t = lane & 3;
    #pragma unroll
    for (int mt = 0; mt < 2; mt++) {
        #pragma unroll
        for (int half = 0; half < 2; half++) {
            int row = bm + wm + mt * 16 + half * 8 + g;
            const float* xrow = (MODE != 0) ? (X + (size_t)row * N) : nullptr;
            #pragma unroll
            for (int nt = 0; nt < 8; nt++) {
                int col = bn + wn + nt * 8 + 2 * t;
                float2 v;
                v.x = acc[mt][nt][half * 2 + 0];
                v.y = acc[mt][nt][half * 2 + 1];
                if (MODE == 1) {
                    float2 xv = *(const float2*)(xrow + col);
                    v.x += xv.x; v.y += xv.y;
                }
                if (MODE == 2) {
                    float2 xv = *(const float2*)(xrow + col);
                    v.x *= xv.x / (1.f + expf(-xv.x));
                    v.y *= xv.y / (1.f + expf(-xv.y));
                }
                if (MODE == 2) {
                    __half2 hv = __floats2half2_rn(v.x, v.y);
                    *(uint32_t*)((__half*)Cout + (size_t)row * N + col) =
                        *(uint32_t*)&hv;
                } else {
                    *(float2*)((float*)Cout + (size_t)row * N + col) = v;
                }
            }
        }
    }
}

// ---------------- RoPE + split qkv -> q,k fp16 [B,H,T,dh] -------------------
#define Q_SCALE (0.125f * 1.44269504088896f)   // 1/sqrt(64) * log2(e)
__global__ void rope_split_h_kernel(const float* __restrict__ qkv,
                                    __half* __restrict__ q,
                                    __half* __restrict__ k) {
    int idx = blockIdx.x * blockDim.x + threadIdx.x;
    int i = idx & 31;
    int h = (idx >> 5) & 15;
    int m = idx >> 9;
    int b = m >> 11;
    int t = m & 2047;

    const float* base = qkv + (size_t)m * (3 * C_DIM) + h * DH + 2 * i;
    float q1 = base[0],     q2 = base[1];
    float k1 = base[C_DIM], k2 = base[C_DIM + 1];

    float freq = expf(-(2.0f * (float)i) * (1.0f / 64.0f) * 9.210340371976184f);
    float th = (float)t * freq;
    float s, c;
    sincosf(th, &s, &c);

    size_t o = ((size_t)(b * H_NUM + h) * T_LEN + t) * DH + 2 * i;
    __half2 qh = __floats2half2_rn((q1 * c - q2 * s) * Q_SCALE,
                                   (q1 * s + q2 * c) * Q_SCALE);
    __half2 kh = __floats2half2_rn(k1 * c - k2 * s, k1 * s + k2 * c);
    *(uint32_t*)(q + o) = *(uint32_t*)&qh;
    *(uint32_t*)(k + o) = *(uint32_t*)&kh;
}

// ---------------- V transpose: qkv v-section -> [B,H,dh,T] fp16 -------------
__global__ void vtrans_h_kernel(const float* __restrict__ qkv,
                                __half* __restrict__ vt) {
    __shared__ float s[64][65];
    int bh = blockIdx.y;
    int b  = bh >> 4;
    int h  = bh & 15;
    int t0 = blockIdx.x * 64;
    int tid = threadIdx.x;

    for (int idx = tid; idx < 64 * 64; idx += 256) {
        int tok = idx >> 6, d = idx & 63;
        s[tok][d] = qkv[(size_t)(b * T_LEN + t0 + tok) * (3 * C_DIM)
                        + 2 * C_DIM + h * DH + d];
    }
    __syncthreads();
    for (int idx = tid; idx < 64 * 32; idx += 256) {
        int d = idx >> 5, tp = idx & 31;
        __half2 hv = __floats2half2_rn(s[2 * tp][d], s[2 * tp + 1][d]);
        *(uint32_t*)(vt + ((size_t)bh * DH + d) * T_LEN + t0 + 2 * tp) =
            *(uint32_t*)&hv;
    }
}

// ---------------- fp16 tensor-core causal flash attention (R9, proven) ------
#define HPAD 72
__global__ __launch_bounds__(128)
void attn_h_kernel(const __half* __restrict__ Q,
                   const __half* __restrict__ Kg,
                   const __half* __restrict__ Vt,
                   __half* __restrict__ O) {
    __shared__ __align__(16) __half sQ[64 * HPAD];   // later: P
    __shared__ __align__(16) __half sK[64 * HPAD];
    __shared__ __align__(16) __half sV[64 * HPAD];

    int bh   = blockIdx.y;
    int b    = bh >> 4;
    int head = bh & 15;
    int q0   = blockIdx.x * 64;
    int tid  = threadIdx.x;
    int warp = tid >> 5;
    int lane = tid & 31;
    int wm   = warp * 16;
    int g    = lane >> 2;
    int t    = lane & 3;
    int l15  = lane & 15;
    int lh   = lane >> 4;

    uint32_t qB = (uint32_t)__cvta_generic_to_shared(sQ);
    uint32_t kB = (uint32_t)__cvta_generic_to_shared(sK);
    uint32_t vB = (uint32_t)__cvta_generic_to_shared(sV);

    const __half* qg = Q + ((size_t)bh * T_LEN + q0) * DH;
    #pragma unroll
    for (int idx = tid; idx < 512; idx += 128) {
        int r = idx >> 3, u = idx & 7;
        *(uint4*)&sQ[r * HPAD + u * 8] = *(const uint4*)(qg + r * DH + u * 8);
    }
    __syncthreads();

    uint32_t qf[4][4];
    #pragma unroll
    for (int kc = 0; kc < 4; kc++) {
        int row = wm + l15;
        int u   = kc * 2 + lh;
        ldsm4(qf[kc][0], qf[kc][1], qf[kc][2], qf[kc][3],
              qB + (uint32_t)(row * HPAD + u * 8) * 2u);
    }
    __syncthreads();   // sQ now reusable as P

    float accO[8][4];
    #pragma unroll
    for (int nt = 0; nt < 8; nt++)
        #pragma unroll
        for (int e = 0; e < 4; e++) accO[nt][e] = 0.f;
    float m0 = -1e30f, m1 = -1e30f, l0 = 0.f, l1 = 0.f;

    int r0 = q0 + wm + g;
    int r1 = r0 + 8;
    int prow0 = (wm + g) * HPAD;
    int prow1 = (wm + g + 8) * HPAD;

    int ntiles = q0 / 64 + 1;
    for (int kt = 0; kt < ntiles; kt++) {
        int ks = kt * 64;
        const __half* kbase = Kg + ((size_t)bh * T_LEN + ks) * DH;
        const __half* vbase = Vt + (size_t)bh * DH * T_LEN + ks;
        #pragma unroll
        for (int idx = tid; idx < 512; idx += 128) {
            int r = idx >> 3, u = idx & 7;
            *(uint4*)&sK[r * HPAD + u * 8] = *(const uint4*)(kbase + r * DH + u * 8);
            *(uint4*)&sV[r * HPAD + u * 8] =
                *(const uint4*)(vbase + (size_t)r * T_LEN + u * 8);
        }
        __syncthreads();

        if (ks <= q0 + wm + 15) {
            float s[8][4];
            #pragma unroll
            for (int nt = 0; nt < 8; nt++)
                #pragma unroll
                for (int e = 0; e < 4; e++) s[nt][e] = 0.f;

            #pragma unroll
            for (int kc = 0; kc < 4; kc++) {
                uint32_t bR[2][2][4];
                #pragma unroll
                for (int kh = 0; kh < 2; kh++)
                    #pragma unroll
                    for (int gb = 0; gb < 2; gb++) {
                        int row = gb * 32 + lane;
                        int u   = kc * 2 + kh;
                        ldsm4(bR[kh][gb][0], bR[kh][gb][1],
                              bR[kh][gb][2], bR[kh][gb][3],
                              kB + (uint32_t)(row * HPAD + u * 8) * 2u);
                    }
                #pragma unroll
                for (int nt = 0; nt < 8; nt++)
                    mma_f16(s[nt], qf[kc][0], qf[kc][1], qf[kc][2], qf[kc][3],
                            bR[0][nt >> 2][nt & 3], bR[1][nt >> 2][nt & 3]);
            }

            if (ks + 63 > q0 + wm) {
                #pragma unroll
                for (int nt = 0; nt < 8; nt++) {
                    int kc = ks + nt * 8 + 2 * t;
                    if (kc     > r0) s[nt][0] = -1e30f;
                    if (kc + 1 > r0) s[nt][1] = -1e30f;
                    if (kc     > r1) s[nt][2] = -1e30f;
                    if (kc + 1 > r1) s[nt][3] = -1e30f;
                }
            }

            float tm0 = -1e30f, tm1 = -1e30f;
            #pragma unroll
            for (int nt = 0; nt < 8; nt++) {
                tm0 = fmaxf(tm0, fmaxf(s[nt][0], s[nt][1]));
                tm1 = fmaxf(tm1, fmaxf(s[nt][2], s[nt][3]));
            }
            tm0 = fmaxf(tm0, __shfl_xor_sync(0xffffffffu, tm0, 1));
            tm0 = fmaxf(tm0, __shfl_xor_sync(0xffffffffu, tm0, 2));
            tm1 = fmaxf(tm1, __shfl_xor_sync(0xffffffffu, tm1, 1));
            tm1 = fmaxf(tm1, __shfl_xor_sync(0xffffffffu, tm1, 2));

            float mn0 = fmaxf(m0, tm0), mn1 = fmaxf(m1, tm1);
            float c0 = exp2f(m0 - mn0), c1 = exp2f(m1 - mn1);

            float ps0 = 0.f, ps1 = 0.f;
            #pragma unroll
            for (int nt = 0; nt < 8; nt++) {
                float pa0 = exp2f(s[nt][0] - mn0), pa1 = exp2f(s[nt][1] - mn0);
                float pb0 = exp2f(s[nt][2] - mn1), pb1 = exp2f(s[nt][3] - mn1);
                ps0 += pa0 + pa1; ps1 += pb0 + pb1;
                __half2 ha = __floats2half2_rn(pa0, pa1);
                __half2 hb = __floats2half2_rn(pb0, pb1);
                int col = nt * 8 + 2 * t;
                *(uint32_t*)&sQ[prow0 + col] = *(uint32_t*)&ha;
                *(uint32_t*)&sQ[prow1 + col] = *(uint32_t*)&hb;
            }
            ps0 += __shfl_xor_sync(0xffffffffu, ps0, 1);
            ps0 += __shfl_xor_sync(0xffffffffu, ps0, 2);
            ps1 += __shfl_xor_sync(0xffffffffu, ps1, 1);
            ps1 += __shfl_xor_sync(0xffffffffu, ps1, 2);

            l0 = l0 * c0 + ps0;
            l1 = l1 * c1 + ps1;
            m0 = mn0; m1 = mn1;

            #pragma unroll
            for (int nt = 0; nt < 8; nt++) {
                accO[nt][0] *= c0; accO[nt][1] *= c0;
                accO[nt][2] *= c1; accO[nt][3] *= c1;
            }
            __syncwarp();

            #pragma unroll
            for (int kc = 0; kc < 4; kc++) {
                uint32_t aP[4];
                {
                    int row = wm + l15;
                    int u   = kc * 2 + lh;
                    ldsm4(aP[0], aP[1], aP[2], aP[3],
                          qB + (uint32_t)(row * HPAD + u * 8) * 2u);
                }
                uint32_t bV[2][2][4];
                #pragma unroll
                for (int kh = 0; kh < 2; kh++)
                    #pragma unroll
                    for (int gb = 0; gb < 2; gb++) {
                        int row = gb * 32 + lane;
                        int u   = kc * 2 + kh;
                        ldsm4(bV[kh][gb][0], bV[kh][gb][1],
                              bV[kh][gb][2], bV[kh][gb][3],
                              vB + (uint32_t)(row * HPAD + u * 8) * 2u);
                    }
                #pragma unroll
                for (int nt = 0; nt < 8; nt++)
                    mma_f16(accO[nt], aP[0], aP[1], aP[2], aP[3],
                            bV[0][nt >> 2][nt & 3], bV[1][nt >> 2][nt & 3]);
            }
        }
        __syncthreads();
    }

    float inv0 = 1.f / l0, inv1 = 1.f / l1;
    __half* o0 = O + ((size_t)(b * T_LEN + r0)) * C_DIM + head * DH;
    __half* o1 = O + ((size_t)(b * T_LEN + r1)) * C_DIM + head * DH;
    #pragma unroll
    for (int nt = 0; nt < 8; nt++) {
        int col = nt * 8 + 2 * t;
        __half2 h0 = __floats2half2_rn(accO[nt][0] * inv0, accO[nt][1] * inv0);
        __half2 h1 = __floats2half2_rn(accO[nt][2] * inv1, accO[nt][3] * inv1);
        *(uint32_t*)(o0 + col) = *(uint32_t*)&h0;
        *(uint32_t*)(o1 + col) = *(uint32_t*)&h1;
    }
}

// ---------------- launch ----------------------------------------------------
extern "C" void kernel_launch(void* const* d_in, const int* in_sizes, int n_in,
                              void* d_out, int out_size) {
    const float* x      = (const float*)d_in[0];
    const float* w_qkv  = (const float*)d_in[1];
    const float* w_proj = (const float*)d_in[2];
    const float* g1     = (const float*)d_in[3];
    const float* g2     = (const float*)d_in[4];
    const float* w1     = (const float*)d_in[5];
    const float* w2     = (const float*)d_in[6];
    const float* w3     = (const float*)d_in[7];
    float* out = (float*)d_out;

    __half *p_h16, *p_q16, *p_k16, *p_v16, *p_o16, *p_ff16, *p_w16;
    float  *p_qkv, *p_x1, *p_ff;
    cudaGetSymbolAddress((void**)&p_h16,  g_h16);
    cudaGetSymbolAddress((void**)&p_qkv,  g_qkv);
    cudaGetSymbolAddress((void**)&p_q16,  g_q16);
    cudaGetSymbolAddress((void**)&p_k16,  g_k16);
    cudaGetSymbolAddress((void**)&p_v16,  g_v16);
    cudaGetSymbolAddress((void**)&p_o16,  g_o16);
    cudaGetSymbolAddress((void**)&p_x1,   g_x1);
    cudaGetSymbolAddress((void**)&p_ff,   g_ff);
    cudaGetSymbolAddress((void**)&p_ff16, g_ff16);
    cudaGetSymbolAddress((void**)&p_w16,  g_w16);

    __half* w_qkv16  = p_w16;
    __half* w_proj16 = w_qkv16  + 3 * C_DIM * C_DIM;
    __half* w116     = w_proj16 + C_DIM * C_DIM;
    __half* w216     = w116     + 4 * C_DIM * C_DIM;
    __half* w316     = w216     + 4 * C_DIM * C_DIM;

    // weight conversion (one-shot per launch)
    f2h_kernel<<<(3 * C_DIM * C_DIM) / (256 * 8), 256>>>(w_qkv,  w_qkv16);
    f2h_kernel<<<(C_DIM * C_DIM)     / (256 * 8), 256>>>(w_proj, w_proj16);
    f2h_kernel<<<(4 * C_DIM * C_DIM) / (256 * 8), 256>>>(w1,     w116);
    f2h_kernel<<<(4 * C_DIM * C_DIM) / (256 * 8), 256>>>(w2,     w216);
    f2h_kernel<<<(4 * C_DIM * C_DIM) / (256 * 8), 256>>>(w3,     w316);

    rmsnorm_h_kernel<<<M_TOK, 256>>>(x, g1, p_h16);
    hgemm_kernel<0><<<dim3(3 * C_DIM / 128, M_TOK / 128), 256>>>(
        p_h16, w_qkv16, nullptr, p_qkv, M_TOK, 3 * C_DIM, C_DIM);
    rope_split_h_kernel<<<(M_TOK * H_NUM * 32) / 256, 256>>>(p_qkv, p_q16, p_k16);
    vtrans_h_kernel<<<dim3(T_LEN / 64, B_NUM * H_NUM), 256>>>(p_qkv, p_v16);
    attn_h_kernel<<<dim3(T_LEN / 64, B_NUM * H_NUM), 128>>>(
        p_q16, p_k16, p_v16, p_o16);
    hgemm_kernel<1><<<dim3(C_DIM / 128, M_TOK / 128), 256>>>(
        p_o16, w_proj16, x, p_x1, M_TOK, C_DIM, C_DIM);
    rmsnorm_h_kernel<<<M_TOK, 256>>>(p_x1, g2, p_h16);
    hgemm_kernel<0><<<dim3(FF_DIM / 128, M_TOK / 128), 256>>>(
        p_h16, w116, nullptr, p_ff, M_TOK, FF_DIM, C_DIM);
    hgemm_kernel<2><<<dim3(FF_DIM / 128, M_TOK / 128), 256>>>(
        p_h16, w316, p_ff, p_ff16, M_TOK, FF_DIM, C_DIM);
    hgemm_kernel<1><<<dim3(C_DIM / 128, M_TOK / 128), 256>>>(
        p_ff16, w216, p_x1, out, M_TOK, C_DIM, FF_DIM);
}

// round 11
// speedup vs baseline: 2.6412x; 1.1217x over previous
#include <cuda_runtime.h>
#include <cuda_fp16.h>
#include <math.h>
#include <stdint.h>

#define C_DIM   1024
#define H_NUM   16
#define DH      64
#define FF_DIM  4096
#define B_NUM   2
#define T_LEN   2048
#define M_TOK   4096   // B*T

// ---------------- scratch (device globals; no allocation allowed) ----------
__device__ __half g_h16 [M_TOK * C_DIM];       // rmsnorm out (fp16)
__device__ float  g_qkv [M_TOK * 3 * C_DIM];
__device__ __half g_q16 [M_TOK * C_DIM];       // [B,H,T,dh] (pre-scaled fp16)
__device__ __half g_k16 [M_TOK * C_DIM];       // [B,H,T,dh] fp16
__device__ __half g_v16 [M_TOK * C_DIM];       // [B,H,dh,T] fp16 (transposed)
__device__ __half g_o16 [M_TOK * C_DIM];       // attention out (fp16)
__device__ float  g_x1  [M_TOK * C_DIM];
__device__ float  g_ff  [M_TOK * FF_DIM];      // a = h2 @ w1^T (fp32)
__device__ __half g_ff16[M_TOK * FF_DIM];      // silu(a)*b (fp16)
__device__ __half g_w16 [(3 + 1 + 4 + 4 + 4) * C_DIM * C_DIM];  // weights fp16

// ---------------- helpers ----------------------------------------------------
__device__ __forceinline__ void mma_f16(float c[4],
                                        uint32_t a0, uint32_t a1, uint32_t a2, uint32_t a3,
                                        uint32_t b0, uint32_t b1) {
    asm volatile(
        "mma.sync.aligned.m16n8k16.row.col.f32.f16.f16.f32 "
        "{%0,%1,%2,%3}, {%4,%5,%6,%7}, {%8,%9}, {%0,%1,%2,%3};\n"
        : "+f"(c[0]), "+f"(c[1]), "+f"(c[2]), "+f"(c[3])
        : "r"(a0), "r"(a1), "r"(a2), "r"(a3), "r"(b0), "r"(b1));
}
__device__ __forceinline__ void ldsm4(uint32_t& r0, uint32_t& r1,
                                      uint32_t& r2, uint32_t& r3, uint32_t addr) {
    asm volatile("ldmatrix.sync.aligned.m8n8.x4.shared.b16 {%0,%1,%2,%3}, [%4];"
                 : "=r"(r0), "=r"(r1), "=r"(r2), "=r"(r3) : "r"(addr));
}
__device__ __forceinline__ void cp16(uint32_t dst, const void* src) {
    asm volatile("cp.async.cg.shared.global [%0], [%1], 16;" :: "r"(dst), "l"(src));
}

// ---------------- fp32 -> fp16 convert (32 elems/thread, coalesced) ---------
__global__ void f2h_kernel(const float* __restrict__ in, __half* __restrict__ out) {
    size_t blk = (size_t)blockIdx.x * 8192 + threadIdx.x * 8;
    #pragma unroll
    for (int j = 0; j < 4; j++) {
        size_t idx = blk + (size_t)j * 2048;
        float4 a = *(const float4*)(in + idx);
        float4 b = *(const float4*)(in + idx + 4);
        __half2 h0 = __floats2half2_rn(a.x, a.y);
        __half2 h1 = __floats2half2_rn(a.z, a.w);
        __half2 h2 = __floats2half2_rn(b.x, b.y);
        __half2 h3 = __floats2half2_rn(b.z, b.w);
        uint4 u;
        u.x = *(uint32_t*)&h0; u.y = *(uint32_t*)&h1;
        u.z = *(uint32_t*)&h2; u.w = *(uint32_t*)&h3;
        *(uint4*)(out + idx) = u;
    }
}

// ---------------- RMSNorm -> fp16 --------------------------------------------
__global__ void rmsnorm_h_kernel(const float* __restrict__ x,
                                 const float* __restrict__ g,
                                 __half* __restrict__ y) {
    int row = blockIdx.x;
    int tid = threadIdx.x;
    const float4* xr = (const float4*)(x + (size_t)row * C_DIM);
    const float4* gr = (const float4*)g;

    float4 xv = xr[tid];
    float ss = xv.x*xv.x + xv.y*xv.y + xv.z*xv.z + xv.w*xv.w;
    #pragma unroll
    for (int off = 16; off > 0; off >>= 1)
        ss += __shfl_xor_sync(0xffffffffu, ss, off);
    __shared__ float red[8];
    if ((tid & 31) == 0) red[tid >> 5] = ss;
    __syncthreads();
    float tot = 0.f;
    #pragma unroll
    for (int i = 0; i < 8; i++) tot += red[i];
    float inv = rsqrtf(tot * (1.0f / C_DIM) + 1e-5f);

    float4 gv = gr[tid];
    __half2 h0 = __floats2half2_rn(xv.x * gv.x * inv, xv.y * gv.y * inv);
    __half2 h1 = __floats2half2_rn(xv.z * gv.z * inv, xv.w * gv.w * inv);
    uint2 u;
    u.x = *(uint32_t*)&h0; u.y = *(uint32_t*)&h1;
    *(uint2*)(y + (size_t)row * C_DIM + tid * 4) = u;
}

// ---------------- fp16 tensor-core GEMM: C[M,N] = A[M,K] @ W[N,K]^T ---------
// Block 128x128, k32 iterations, 3-stage cp.async pipeline (wait_group 1).
// Stage = 128 rows x 32 halves (64B rows; swizzle u ^= (row>>1)&3).
// 8 warps (4m x 2n), warp tile 32x64, fragments via ldmatrix.x4.
// MODE 0: fp32 out  MODE 1: fp32 out + X residual  MODE 2: fp16 out, silu(X)*acc
#define GST 3
template <int MODE>
__global__ __launch_bounds__(256, 2)
void hgemm_kernel(const __half* __restrict__ A, const __half* __restrict__ W,
                  const float* X, void* Cout, int M, int N, int K) {
    __shared__ __align__(16) __half sA[GST][128 * 32];
    __shared__ __align__(16) __half sB[GST][128 * 32];

    int tid  = threadIdx.x;
    int bm   = blockIdx.y * 128;
    int bn   = blockIdx.x * 128;
    int warp = tid >> 5;
    int lane = tid & 31;
    int wm   = (warp >> 1) * 32;
    int wn   = (warp & 1) * 64;

    // store mapping: each thread writes 2 16B units for A and 2 for B per k32
    uint32_t dstOff[2];
    int srow[2], su[2];
    #pragma unroll
    for (int j = 0; j < 2; j++) {
        int idx = tid + 256 * j;
        int row = idx >> 2, u = idx & 3;
        int uz  = u ^ ((row >> 1) & 3);
        dstOff[j] = (uint32_t)(row * 32 + uz * 8) * 2u;
        srow[j] = row; su[j] = u;
    }

    uint32_t aBase = (uint32_t)__cvta_generic_to_shared(&sA[0][0]);
    uint32_t bBase = (uint32_t)__cvta_generic_to_shared(&sB[0][0]);

    // ldmatrix offsets
    int l15 = lane & 15, lh = lane >> 4;
    uint32_t offA[2][2];      // [q(k16 half)][mt]
    #pragma unroll
    for (int q = 0; q < 2; q++)
        #pragma unroll
        for (int mt = 0; mt < 2; mt++) {
            int row = wm + mt * 16 + l15;
            int u   = 2 * q + lh;
            int uz  = u ^ ((row >> 1) & 3);
            offA[q][mt] = (uint32_t)(row * 32 + uz * 8) * 2u;
        }
    uint32_t offB[2][2][2];   // [q][k-octet][n-group of 32]
    #pragma unroll
    for (int q = 0; q < 2; q++)
        #pragma unroll
        for (int kh = 0; kh < 2; kh++)
            #pragma unroll
            for (int gb = 0; gb < 2; gb++) {
                int row = wn + gb * 32 + lane;
                int u   = 2 * q + kh;
                int uz  = u ^ ((row >> 1) & 3);
                offB[q][kh][gb] = (uint32_t)(row * 32 + uz * 8) * 2u;
            }

    float acc[2][8][4];
    #pragma unroll
    for (int mt = 0; mt < 2; mt++)
        #pragma unroll
        for (int nt = 0; nt < 8; nt++)
            #pragma unroll
            for (int e = 0; e < 4; e++) acc[mt][nt][e] = 0.f;

    int NC = K >> 5;   // k32 chunks

    // prologue: stages 0,1 in flight
    #pragma unroll
    for (int s = 0; s < 2; s++) {
        #pragma unroll
        for (int j = 0; j < 2; j++) {
            cp16(aBase + s * 8192u + dstOff[j],
                 A + (size_t)(bm + srow[j]) * K + s * 32 + su[j] * 8);
            cp16(bBase + s * 8192u + dstOff[j],
                 W + (size_t)(bn + srow[j]) * K + s * 32 + su[j] * 8);
        }
        asm volatile("cp.async.commit_group;" ::: "memory");
    }

    int st = 0, sn = 2;
    for (int ck = 0; ck < NC; ck++) {
        asm volatile("cp.async.wait_group 1;" ::: "memory");
        __syncthreads();

        uint32_t tA = aBase + st * 8192u;
        uint32_t tB = bBase + st * 8192u;
        #pragma unroll
        for (int q = 0; q < 2; q++) {
            uint32_t aR[2][4], bR[2][2][4];
            ldsm4(aR[0][0], aR[0][1], aR[0][2], aR[0][3], tA + offA[q][0]);
            ldsm4(aR[1][0], aR[1][1], aR[1][2], aR[1][3], tA + offA[q][1]);
            #pragma unroll
            for (int kh = 0; kh < 2; kh++)
                #pragma unroll
                for (int gb = 0; gb < 2; gb++)
                    ldsm4(bR[kh][gb][0], bR[kh][gb][1], bR[kh][gb][2], bR[kh][gb][3],
                          tB + offB[q][kh][gb]);
            #pragma unroll
            for (int mt = 0; mt < 2; mt++)
                #pragma unroll
                for (int nt = 0; nt < 8; nt++)
                    mma_f16(acc[mt][nt],
                            aR[mt][0], aR[mt][1], aR[mt][2], aR[mt][3],
                            bR[0][nt >> 2][nt & 3], bR[1][nt >> 2][nt & 3]);
        }

        int cn = ck + 2;
        if (cn < NC) {
            uint32_t nA = aBase + sn * 8192u;
            uint32_t nB = bBase + sn * 8192u;
            #pragma unroll
            for (int j = 0; j < 2; j++) {
                cp16(nA + dstOff[j],
                     A + (size_t)(bm + srow[j]) * K + cn * 32 + su[j] * 8);
                cp16(nB + dstOff[j],
                     W + (size_t)(bn + srow[j]) * K + cn * 32 + su[j] * 8);
            }
        }
        asm volatile("cp.async.commit_group;" ::: "memory");

        st = (st + 1 == GST) ? 0 : st + 1;
        sn = (sn + 1 == GST) ? 0 : sn + 1;
    }

    // epilogue
    int g = lane >> 2;
    int t = lane & 3;
    #pragma unroll
    for (int mt = 0; mt < 2; mt++) {
        #pragma unroll
        for (int half = 0; half < 2; half++) {
            int row = bm + wm + mt * 16 + half * 8 + g;
            const float* xrow = (MODE != 0) ? (X + (size_t)row * N) : nullptr;
            #pragma unroll
            for (int nt = 0; nt < 8; nt++) {
                int col = bn + wn + nt * 8 + 2 * t;
                float2 v;
                v.x = acc[mt][nt][half * 2 + 0];
                v.y = acc[mt][nt][half * 2 + 1];
                if (MODE == 1) {
                    float2 xv = *(const float2*)(xrow + col);
                    v.x += xv.x; v.y += xv.y;
                }
                if (MODE == 2) {
                    float2 xv = *(const float2*)(xrow + col);
                    v.x *= xv.x / (1.f + expf(-xv.x));
                    v.y *= xv.y / (1.f + expf(-xv.y));
                }
                if (MODE == 2) {
                    __half2 hv = __floats2half2_rn(v.x, v.y);
                    *(uint32_t*)((__half*)Cout + (size_t)row * N + col) =
                        *(uint32_t*)&hv;
                } else {
                    *(float2*)((float*)Cout + (size_t)row * N + col) = v;
                }
            }
        }
    }
}

// ---------------- RoPE + split qkv -> q,k fp16 [B,H,T,dh] -------------------
#define Q_SCALE (0.125f * 1.44269504088896f)   // 1/sqrt(64) * log2(e)
__global__ void rope_split_h_kernel(const float* __restrict__ qkv,
                                    __half* __restrict__ q,
                                    __half* __restrict__ k) {
    int idx = blockIdx.x * blockDim.x + threadIdx.x;
    int i = idx & 31;
    int h = (idx >> 5) & 15;
    int m = idx >> 9;
    int b = m >> 11;
    int t = m & 2047;

    const float* base = qkv + (size_t)m * (3 * C_DIM) + h * DH + 2 * i;
    float q1 = base[0],     q2 = base[1];
    float k1 = base[C_DIM], k2 = base[C_DIM + 1];

    float freq = expf(-(2.0f * (float)i) * (1.0f / 64.0f) * 9.210340371976184f);
    float th = (float)t * freq;
    float s, c;
    sincosf(th, &s, &c);

    size_t o = ((size_t)(b * H_NUM + h) * T_LEN + t) * DH + 2 * i;
    __half2 qh = __floats2half2_rn((q1 * c - q2 * s) * Q_SCALE,
                                   (q1 * s + q2 * c) * Q_SCALE);
    __half2 kh = __floats2half2_rn(k1 * c - k2 * s, k1 * s + k2 * c);
    *(uint32_t*)(q + o) = *(uint32_t*)&qh;
    *(uint32_t*)(k + o) = *(uint32_t*)&kh;
}

// ---------------- V transpose: qkv v-section -> [B,H,dh,T] fp16 -------------
__global__ void vtrans_h_kernel(const float* __restrict__ qkv,
                                __half* __restrict__ vt) {
    __shared__ float s[64][65];
    int bh = blockIdx.y;
    int b  = bh >> 4;
    int h  = bh & 15;
    int t0 = blockIdx.x * 64;
    int tid = threadIdx.x;

    for (int idx = tid; idx < 64 * 64; idx += 256) {
        int tok = idx >> 6, d = idx & 63;
        s[tok][d] = qkv[(size_t)(b * T_LEN + t0 + tok) * (3 * C_DIM)
                        + 2 * C_DIM + h * DH + d];
    }
    __syncthreads();
    for (int idx = tid; idx < 64 * 32; idx += 256) {
        int d = idx >> 5, tp = idx & 31;
        __half2 hv = __floats2half2_rn(s[2 * tp][d], s[2 * tp + 1][d]);
        *(uint32_t*)(vt + ((size_t)bh * DH + d) * T_LEN + t0 + 2 * tp) =
            *(uint32_t*)&hv;
    }
}

// ---------------- fp16 tensor-core causal flash attention -------------------
// f16x2 approx softmax; row-sum l via ones-column mma (same rescale as accO).
#define HPAD 72
#define ONES16 0x3C003C00u
__global__ __launch_bounds__(128)
void attn_h_kernel(const __half* __restrict__ Q,
                   const __half* __restrict__ Kg,
                   const __half* __restrict__ Vt,
                   __half* __restrict__ O) {
    __shared__ __align__(16) __half sQ[64 * HPAD];   // later: P
    __shared__ __align__(16) __half sK[64 * HPAD];
    __shared__ __align__(16) __half sV[64 * HPAD];

    int bh   = blockIdx.y;
    int b    = bh >> 4;
    int head = bh & 15;
    int q0   = blockIdx.x * 64;
    int tid  = threadIdx.x;
    int warp = tid >> 5;
    int lane = tid & 31;
    int wm   = warp * 16;
    int g    = lane >> 2;
    int t    = lane & 3;
    int l15  = lane & 15;
    int lh   = lane >> 4;

    uint32_t qB = (uint32_t)__cvta_generic_to_shared(sQ);
    uint32_t kB = (uint32_t)__cvta_generic_to_shared(sK);
    uint32_t vB = (uint32_t)__cvta_generic_to_shared(sV);

    const __half* qg = Q + ((size_t)bh * T_LEN + q0) * DH;
    #pragma unroll
    for (int idx = tid; idx < 512; idx += 128) {
        int r = idx >> 3, u = idx & 7;
        *(uint4*)&sQ[r * HPAD + u * 8] = *(const uint4*)(qg + r * DH + u * 8);
    }
    __syncthreads();

    uint32_t qf[4][4];
    #pragma unroll
    for (int kc = 0; kc < 4; kc++) {
        int row = wm + l15;
        int u   = kc * 2 + lh;
        ldsm4(qf[kc][0], qf[kc][1], qf[kc][2], qf[kc][3],
              qB + (uint32_t)(row * HPAD + u * 8) * 2u);
    }
    __syncthreads();   // sQ now reusable as P

    float accO[8][4];
    #pragma unroll
    for (int nt = 0; nt < 8; nt++)
        #pragma unroll
        for (int e = 0; e < 4; e++) accO[nt][e] = 0.f;
    float lacc[4] = {0.f, 0.f, 0.f, 0.f};
    float m0 = -1e30f, m1 = -1e30f;

    int r0 = q0 + wm + g;
    int r1 = r0 + 8;
    int prow0 = (wm + g) * HPAD;
    int prow1 = (wm + g + 8) * HPAD;

    int ntiles = q0 / 64 + 1;
    for (int kt = 0; kt < ntiles; kt++) {
        int ks = kt * 64;
        const __half* kbase = Kg + ((size_t)bh * T_LEN + ks) * DH;
        const __half* vbase = Vt + (size_t)bh * DH * T_LEN + ks;
        #pragma unroll
        for (int idx = tid; idx < 512; idx += 128) {
            int r = idx >> 3, u = idx & 7;
            *(uint4*)&sK[r * HPAD + u * 8] = *(const uint4*)(kbase + r * DH + u * 8);
            *(uint4*)&sV[r * HPAD + u * 8] =
                *(const uint4*)(vbase + (size_t)r * T_LEN + u * 8);
        }
        __syncthreads();

        if (ks <= q0 + wm + 15) {
            // ---- S = Q @ K^T ----
            float s[8][4];
            #pragma unroll
            for (int nt = 0; nt < 8; nt++)
                #pragma unroll
                for (int e = 0; e < 4; e++) s[nt][e] = 0.f;

            #pragma unroll
            for (int kc = 0; kc < 4; kc++) {
                uint32_t bR[2][2][4];
                #pragma unroll
                for (int kh = 0; kh < 2; kh++)
                    #pragma unroll
                    for (int gb = 0; gb < 2; gb++) {
                        int row = gb * 32 + lane;
                        int u   = kc * 2 + kh;
                        ldsm4(bR[kh][gb][0], bR[kh][gb][1],
                              bR[kh][gb][2], bR[kh][gb][3],
                              kB + (uint32_t)(row * HPAD + u * 8) * 2u);
                    }
                #pragma unroll
                for (int nt = 0; nt < 8; nt++)
                    mma_f16(s[nt], qf[kc][0], qf[kc][1], qf[kc][2], qf[kc][3],
                            bR[0][nt >> 2][nt & 3], bR[1][nt >> 2][nt & 3]);
            }

            // ---- causal mask ----
            if (ks + 63 > q0 + wm) {
                #pragma unroll
                for (int nt = 0; nt < 8; nt++) {
                    int kc = ks + nt * 8 + 2 * t;
                    if (kc     > r0) s[nt][0] = -1e30f;
                    if (kc + 1 > r0) s[nt][1] = -1e30f;
                    if (kc     > r1) s[nt][2] = -1e30f;
                    if (kc + 1 > r1) s[nt][3] = -1e30f;
                }
            }

            // ---- online softmax (log2 domain; f16x2 approx exp) ----
            float tm0 = -1e30f, tm1 = -1e30f;
            #pragma unroll
            for (int nt = 0; nt < 8; nt++) {
                tm0 = fmaxf(tm0, fmaxf(s[nt][0], s[nt][1]));
                tm1 = fmaxf(tm1, fmaxf(s[nt][2], s[nt][3]));
            }
            tm0 = fmaxf(tm0, __shfl_xor_sync(0xffffffffu, tm0, 1));
            tm0 = fmaxf(tm0, __shfl_xor_sync(0xffffffffu, tm0, 2));
            tm1 = fmaxf(tm1, __shfl_xor_sync(0xffffffffu, tm1, 1));
            tm1 = fmaxf(tm1, __shfl_xor_sync(0xffffffffu, tm1, 2));

            float mn0 = fmaxf(m0, tm0), mn1 = fmaxf(m1, tm1);
            float c0 = exp2f(m0 - mn0), c1 = exp2f(m1 - mn1);
            m0 = mn0; m1 = mn1;

            #pragma unroll
            for (int nt = 0; nt < 8; nt++) {
                uint32_t ha, hb;
                asm("cvt.rn.f16x2.f32 %0, %1, %2;" : "=r"(ha)
                    : "f"(s[nt][1] - mn0), "f"(s[nt][0] - mn0));
                asm("cvt.rn.f16x2.f32 %0, %1, %2;" : "=r"(hb)
                    : "f"(s[nt][3] - mn1), "f"(s[nt][2] - mn1));
                asm("ex2.approx.f16x2 %0, %1;" : "=r"(ha) : "r"(ha));
                asm("ex2.approx.f16x2 %0, %1;" : "=r"(hb) : "r"(hb));
                int col = nt * 8 + 2 * t;
                *(uint32_t*)&sQ[prow0 + col] = ha;
                *(uint32_t*)&sQ[prow1 + col] = hb;
            }

            #pragma unroll
            for (int nt = 0; nt < 8; nt++) {
                accO[nt][0] *= c0; accO[nt][1] *= c0;
                accO[nt][2] *= c1; accO[nt][3] *= c1;
            }
            lacc[0] *= c0; lacc[1] *= c0;
            lacc[2] *= c1; lacc[3] *= c1;
            __syncwarp();

            // ---- O += P @ V ; l += P @ 1 ----
            #pragma unroll
            for (int kc = 0; kc < 4; kc++) {
                uint32_t aP[4];
                {
                    int row = wm + l15;
                    int u   = kc * 2 + lh;
                    ldsm4(aP[0], aP[1], aP[2], aP[3],
                          qB + (uint32_t)(row * HPAD + u * 8) * 2u);
                }
                mma_f16(lacc, aP[0], aP[1], aP[2], aP[3], ONES16, ONES16);
                uint32_t bV[2][2][4];
                #pragma unroll
                for (int kh = 0; kh < 2; kh++)
                    #pragma unroll
                    for (int gb = 0; gb < 2; gb++) {
                        int row = gb * 32 + lane;
                        int u   = kc * 2 + kh;
                        ldsm4(bV[kh][gb][0], bV[kh][gb][1],
                              bV[kh][gb][2], bV[kh][gb][3],
                              vB + (uint32_t)(row * HPAD + u * 8) * 2u);
                    }
                #pragma unroll
                for (int nt = 0; nt < 8; nt++)
                    mma_f16(accO[nt], aP[0], aP[1], aP[2], aP[3],
                            bV[0][nt >> 2][nt & 3], bV[1][nt >> 2][nt & 3]);
            }
        }
        __syncthreads();
    }

    // ---- epilogue (fp16 out) ----
    float inv0 = 1.f / lacc[0], inv1 = 1.f / lacc[2];
    __half* o0 = O + ((size_t)(b * T_LEN + r0)) * C_DIM + head * DH;
    __half* o1 = O + ((size_t)(b * T_LEN + r1)) * C_DIM + head * DH;
    #pragma unroll
    for (int nt = 0; nt < 8; nt++) {
        int col = nt * 8 + 2 * t;
        __half2 h0 = __floats2half2_rn(accO[nt][0] * inv0, accO[nt][1] * inv0);
        __half2 h1 = __floats2half2_rn(accO[nt][2] * inv1, accO[nt][3] * inv1);
        *(uint32_t*)(o0 + col) = *(uint32_t*)&h0;
        *(uint32_t*)(o1 + col) = *(uint32_t*)&h1;
    }
}

// ---------------- launch ----------------------------------------------------
extern "C" void kernel_launch(void* const* d_in, const int* in_sizes, int n_in,
                              void* d_out, int out_size) {
    const float* x      = (const float*)d_in[0];
    const float* w_qkv  = (const float*)d_in[1];
    const float* w_proj = (const float*)d_in[2];
    const float* g1     = (const float*)d_in[3];
    const float* g2     = (const float*)d_in[4];
    const float* w1     = (const float*)d_in[5];
    const float* w2     = (const float*)d_in[6];
    const float* w3     = (const float*)d_in[7];
    float* out = (float*)d_out;

    __half *p_h16, *p_q16, *p_k16, *p_v16, *p_o16, *p_ff16, *p_w16;
    float  *p_qkv, *p_x1, *p_ff;
    cudaGetSymbolAddress((void**)&p_h16,  g_h16);
    cudaGetSymbolAddress((void**)&p_qkv,  g_qkv);
    cudaGetSymbolAddress((void**)&p_q16,  g_q16);
    cudaGetSymbolAddress((void**)&p_k16,  g_k16);
    cudaGetSymbolAddress((void**)&p_v16,  g_v16);
    cudaGetSymbolAddress((void**)&p_o16,  g_o16);
    cudaGetSymbolAddress((void**)&p_x1,   g_x1);
    cudaGetSymbolAddress((void**)&p_ff,   g_ff);
    cudaGetSymbolAddress((void**)&p_ff16, g_ff16);
    cudaGetSymbolAddress((void**)&p_w16,  g_w16);

    __half* w_qkv16  = p_w16;
    __half* w_proj16 = w_qkv16  + 3 * C_DIM * C_DIM;
    __half* w116     = w_proj16 + C_DIM * C_DIM;
    __half* w216     = w116     + 4 * C_DIM * C_DIM;
    __half* w316     = w216     + 4 * C_DIM * C_DIM;

    // weight conversion (one-shot per launch; 8192 elems/block)
    f2h_kernel<<<(3 * C_DIM * C_DIM) / 8192, 256>>>(w_qkv,  w_qkv16);
    f2h_kernel<<<(C_DIM * C_DIM)     / 8192, 256>>>(w_proj, w_proj16);
    f2h_kernel<<<(4 * C_DIM * C_DIM) / 8192, 256>>>(w1,     w116);
    f2h_kernel<<<(4 * C_DIM * C_DIM) / 8192, 256>>>(w2,     w216);
    f2h_kernel<<<(4 * C_DIM * C_DIM) / 8192, 256>>>(w3,     w316);

    rmsnorm_h_kernel<<<M_TOK, 256>>>(x, g1, p_h16);
    hgemm_kernel<0><<<dim3(3 * C_DIM / 128, M_TOK / 128), 256>>>(
        p_h16, w_qkv16, nullptr, p_qkv, M_TOK, 3 * C_DIM, C_DIM);
    rope_split_h_kernel<<<(M_TOK * H_NUM * 32) / 256, 256>>>(p_qkv, p_q16, p_k16);
    vtrans_h_kernel<<<dim3(T_LEN / 64, B_NUM * H_NUM), 256>>>(p_qkv, p_v16);
    attn_h_kernel<<<dim3(T_LEN / 64, B_NUM * H_NUM), 128>>>(
        p_q16, p_k16, p_v16, p_o16);
    hgemm_kernel<1><<<dim3(C_DIM / 128, M_TOK / 128), 256>>>(
        p_o16, w_proj16, x, p_x1, M_TOK, C_DIM, C_DIM);
    rmsnorm_h_kernel<<<M_TOK, 256>>>(p_x1, g2, p_h16);
    hgemm_kernel<0><<<dim3(FF_DIM / 128, M_TOK / 128), 256>>>(
        p_h16, w116, nullptr, p_ff, M_TOK, FF_DIM, C_DIM);
    hgemm_kernel<2><<<dim3(FF_DIM / 128, M_TOK / 128), 256>>>(
        p_h16, w316, p_ff, p_ff16, M_TOK, FF_DIM, C_DIM);
    hgemm_kernel<1><<<dim3(C_DIM / 128, M_TOK / 128), 256>>>(
        p_ff16, w216, p_x1, out, M_TOK, C_DIM, FF_DIM);
}